// round 1
// baseline (speedup 1.0000x reference)
#include <cuda_runtime.h>
#include <math.h>

// Problem constants
#define BB 16
#define TT 2048
#define DD 1024
#define MROWS (BB * TT)   // 32768
#define LN_EPS 1e-5f

// Scratch: __device__ globals (no cudaMalloc allowed)
__device__ float g_u [(size_t)MROWS * DD];   // sigmoid(gx)
__device__ float g_vx[(size_t)MROWS * DD];   // vx, later reused as y (scan output)
__device__ float g_c [(size_t)MROWS * DD];   // cand

// ---------------------------------------------------------------------------
// SGEMM (NT): C[m,n] = sum_k A[m,k] * B[n,k].  A:[M,K] row-major, B:[N,K] row-major.
// 128x128 tile, BK=16, 256 threads, 8x8 per thread.
// MODE 1: GEMM1 epilogue — n<DD: g_u = sigmoid(acc); n>=DD: g_vx = acc.
// MODE 0: plain store to C0 (ld = N).
// ---------------------------------------------------------------------------
#define BM 128
#define BN 128
#define BK 16

template <int MODE>
__global__ __launch_bounds__(256, 2)
void sgemm_nt(const float* __restrict__ A, const float* __restrict__ Bmat,
              float* __restrict__ C0, int K, int N)
{
    __shared__ float As[BK][BM + 4];
    __shared__ float Bs[BK][BN + 4];

    const int tid = threadIdx.x;
    const int bm = blockIdx.y * BM;
    const int bn = blockIdx.x * BN;

    const int lr = tid >> 2;        // 0..63
    const int lk = (tid & 3) * 4;   // 0,4,8,12

    const float* Ab = A    + (size_t)bm * K;
    const float* Bb = Bmat + (size_t)bn * K;

    float acc[8][8];
#pragma unroll
    for (int i = 0; i < 8; i++)
#pragma unroll
        for (int j = 0; j < 8; j++) acc[i][j] = 0.f;

    const int mt = (tid >> 4) * 8;
    const int nt = (tid & 15) * 8;

    for (int k0 = 0; k0 < K; k0 += BK) {
#pragma unroll
        for (int r = 0; r < 2; r++) {
            int row = lr + 64 * r;
            float4 va = *(const float4*)(Ab + (size_t)row * K + k0 + lk);
            As[lk + 0][row] = va.x;
            As[lk + 1][row] = va.y;
            As[lk + 2][row] = va.z;
            As[lk + 3][row] = va.w;
            float4 vb = *(const float4*)(Bb + (size_t)row * K + k0 + lk);
            Bs[lk + 0][row] = vb.x;
            Bs[lk + 1][row] = vb.y;
            Bs[lk + 2][row] = vb.z;
            Bs[lk + 3][row] = vb.w;
        }
        __syncthreads();

#pragma unroll
        for (int kk = 0; kk < BK; kk++) {
            float ra[8], rb[8];
            float4 a0 = *(const float4*)&As[kk][mt];
            float4 a1 = *(const float4*)&As[kk][mt + 4];
            float4 b0 = *(const float4*)&Bs[kk][nt];
            float4 b1 = *(const float4*)&Bs[kk][nt + 4];
            ra[0]=a0.x; ra[1]=a0.y; ra[2]=a0.z; ra[3]=a0.w;
            ra[4]=a1.x; ra[5]=a1.y; ra[6]=a1.z; ra[7]=a1.w;
            rb[0]=b0.x; rb[1]=b0.y; rb[2]=b0.z; rb[3]=b0.w;
            rb[4]=b1.x; rb[5]=b1.y; rb[6]=b1.z; rb[7]=b1.w;
#pragma unroll
            for (int i = 0; i < 8; i++)
#pragma unroll
                for (int j = 0; j < 8; j++)
                    acc[i][j] = fmaf(ra[i], rb[j], acc[i][j]);
        }
        __syncthreads();
    }

    if (MODE == 1) {
        // Whole block is on one side of the D boundary (BN=128 divides DD=1024)
        if (bn + nt < DD) {
#pragma unroll
            for (int i = 0; i < 8; i++) {
                size_t base = (size_t)(bm + mt + i) * DD + (bn + nt);
                float4 o0, o1;
                o0.x = 1.f / (1.f + expf(-acc[i][0]));
                o0.y = 1.f / (1.f + expf(-acc[i][1]));
                o0.z = 1.f / (1.f + expf(-acc[i][2]));
                o0.w = 1.f / (1.f + expf(-acc[i][3]));
                o1.x = 1.f / (1.f + expf(-acc[i][4]));
                o1.y = 1.f / (1.f + expf(-acc[i][5]));
                o1.z = 1.f / (1.f + expf(-acc[i][6]));
                o1.w = 1.f / (1.f + expf(-acc[i][7]));
                *(float4*)&g_u[base]     = o0;
                *(float4*)&g_u[base + 4] = o1;
            }
        } else {
#pragma unroll
            for (int i = 0; i < 8; i++) {
                size_t base = (size_t)(bm + mt + i) * DD + (bn + nt - DD);
                float4 o0 = make_float4(acc[i][0], acc[i][1], acc[i][2], acc[i][3]);
                float4 o1 = make_float4(acc[i][4], acc[i][5], acc[i][6], acc[i][7]);
                *(float4*)&g_vx[base]     = o0;
                *(float4*)&g_vx[base + 4] = o1;
            }
        }
    } else {
#pragma unroll
        for (int i = 0; i < 8; i++) {
            size_t base = (size_t)(bm + mt + i) * N + (bn + nt);
            float4 o0 = make_float4(acc[i][0], acc[i][1], acc[i][2], acc[i][3]);
            float4 o1 = make_float4(acc[i][4], acc[i][5], acc[i][6], acc[i][7]);
            *(float4*)&C0[base]     = o0;
            *(float4*)&C0[base + 4] = o1;
        }
    }
}

// ---------------------------------------------------------------------------
// Sequential diagonal recurrence. One thread per (b, d). Writes y into g_vx.
// h_t = u*h + (1-u)*c = fma(u, h-c, c)
// ---------------------------------------------------------------------------
__global__ __launch_bounds__(256)
void scan_kernel()
{
    int idx = blockIdx.x * blockDim.x + threadIdx.x;   // 0 .. B*D-1
    int b = idx >> 10;          // / DD
    int d = idx & (DD - 1);
    size_t base = (size_t)b * TT * DD + d;
    float h = 0.f;
#pragma unroll 4
    for (int t = 0; t < TT; t++) {
        size_t off = base + (size_t)t * DD;
        float u = g_u[off];
        float c = g_c[off];
        h = fmaf(u, h - c, c);
        g_vx[off] = h;
    }
}

// ---------------------------------------------------------------------------
// LayerNorm over D per row. 256 threads, float4 each (D=1024).
// ---------------------------------------------------------------------------
__global__ __launch_bounds__(256)
void ln_kernel(const float* __restrict__ gamma, const float* __restrict__ beta,
               float* __restrict__ out)
{
    int row = blockIdx.x;
    int t = threadIdx.x;
    const float4* yr = (const float4*)(g_vx + (size_t)row * DD);
    float4 v = yr[t];
    float s = v.x + v.y + v.z + v.w;
    float q = v.x*v.x + v.y*v.y + v.z*v.z + v.w*v.w;

#pragma unroll
    for (int o = 16; o; o >>= 1) {
        s += __shfl_xor_sync(0xFFFFFFFFu, s, o);
        q += __shfl_xor_sync(0xFFFFFFFFu, q, o);
    }
    __shared__ float sw[8], qw[8];
    __shared__ float mu_s, inv_s;
    int w = t >> 5, l = t & 31;
    if (l == 0) { sw[w] = s; qw[w] = q; }
    __syncthreads();
    if (t == 0) {
        float S = 0.f, Q = 0.f;
#pragma unroll
        for (int i = 0; i < 8; i++) { S += sw[i]; Q += qw[i]; }
        float mu = S * (1.f / DD);
        float var = Q * (1.f / DD) - mu * mu;
        mu_s = mu;
        inv_s = rsqrtf(var + LN_EPS);
    }
    __syncthreads();
    float mu = mu_s, inv = inv_s;

    const float4* g4 = (const float4*)gamma;
    const float4* b4 = (const float4*)beta;
    float4 gv = g4[t], bv = b4[t];
    float4 o;
    o.x = (v.x - mu) * inv * gv.x + bv.x;
    o.y = (v.y - mu) * inv * gv.y + bv.y;
    o.z = (v.z - mu) * inv * gv.z + bv.z;
    o.w = (v.w - mu) * inv * gv.w + bv.w;
    ((float4*)(out + (size_t)row * DD))[t] = o;
}

// ---------------------------------------------------------------------------
extern "C" void kernel_launch(void* const* d_in, const int* in_sizes, int n_in,
                              void* d_out, int out_size)
{
    const float* x       = (const float*)d_in[0];
    const float* W_in    = (const float*)d_in[1];
    const float* W_state = (const float*)d_in[2];
    const float* gamma   = (const float*)d_in[3];
    const float* beta    = (const float*)d_in[4];
    float* out = (float*)d_out;

    float *p_vx = nullptr, *p_c = nullptr;
    cudaGetSymbolAddress((void**)&p_vx, g_vx);
    cudaGetSymbolAddress((void**)&p_c,  g_c);

    // GEMM1: [32768 x 1024] @ [2048 x 1024]^T -> u / vx
    {
        dim3 grid(2 * DD / BN, MROWS / BM);   // (16, 256)
        sgemm_nt<1><<<grid, 256>>>(x, W_in, nullptr, DD, 2 * DD);
    }
    // GEMM2: [32768 x 1024] @ [1024 x 1024]^T -> cand
    {
        dim3 grid(DD / BN, MROWS / BM);       // (8, 256)
        sgemm_nt<0><<<grid, 256>>>(p_vx, W_state, p_c, DD, DD);
    }
    // Scan over T (writes y into g_vx)
    scan_kernel<<<(BB * DD) / 256, 256>>>();
    // LayerNorm -> out
    ln_kernel<<<MROWS, 256>>>(gamma, beta, out);
}

// round 3
// speedup vs baseline: 2.4609x; 2.4609x over previous
#include <cuda_runtime.h>
#include <cuda_bf16.h>
#include <math.h>
#include <stdint.h>

#define BB 16
#define TT 2048
#define DD 1024
#define MROWS (BB * TT)       // 32768
#define LN_EPS 1e-5f

// ---- GEMM tiling ----
#define BM 128
#define BN 128
#define BK 32                  // bf16 elems per k-chunk
#define NSTAGE 3
#define ROWB 80                // padded smem row: 40 bf16 = 80B (conflict-free ldmatrix)
#define A_HI_OFF 0
#define A_LO_OFF (BM * ROWB)                     // 10240
#define B_HI_OFF (2 * BM * ROWB)                 // 20480
#define B_LO_OFF (2 * BM * ROWB + BN * ROWB)     // 30720
#define STAGE_B  (2 * BM * ROWB + 2 * BN * ROWB) // 40960
#define SMEM_TOTAL (NSTAGE * STAGE_B)            // 122880
#define GROUP_M 16

// ---- scratch (__device__ globals; no cudaMalloc allowed) ----
__device__ __nv_bfloat16 g_xhi[(size_t)MROWS * DD];
__device__ __nv_bfloat16 g_xlo[(size_t)MROWS * DD];
__device__ __nv_bfloat16 g_whi[(size_t)2 * DD * DD];
__device__ __nv_bfloat16 g_wlo[(size_t)2 * DD * DD];
__device__ __nv_bfloat16 g_shi[(size_t)DD * DD];
__device__ __nv_bfloat16 g_slo[(size_t)DD * DD];
__device__ __nv_bfloat16 g_vhi[(size_t)MROWS * DD];
__device__ __nv_bfloat16 g_vlo[(size_t)MROWS * DD];
__device__ float g_u[(size_t)MROWS * DD];
__device__ float g_c[(size_t)MROWS * DD];

// ============================ device helpers ============================
__device__ __forceinline__ uint32_t smem_u32(const void* p) {
    uint32_t a;
    asm("{ .reg .u64 t; cvta.to.shared.u64 t, %1; cvt.u32.u64 %0, t; }" : "=r"(a) : "l"(p));
    return a;
}
__device__ __forceinline__ void cp16(uint32_t dst, const void* src) {
    asm volatile("cp.async.cg.shared.global [%0], [%1], 16;" :: "r"(dst), "l"(src));
}
__device__ __forceinline__ void cp_commit() {
    asm volatile("cp.async.commit_group;" ::: "memory");
}
template <int N>
__device__ __forceinline__ void cp_wait() {
    asm volatile("cp.async.wait_group %0;" :: "n"(N) : "memory");
}
__device__ __forceinline__ void ldsm4(uint32_t* r, uint32_t a) {
    asm volatile("ldmatrix.sync.aligned.m8n8.x4.shared.b16 {%0,%1,%2,%3}, [%4];"
                 : "=r"(r[0]), "=r"(r[1]), "=r"(r[2]), "=r"(r[3]) : "r"(a));
}
__device__ __forceinline__ void mma16816(float* c, const uint32_t* a, const uint32_t* b) {
    asm volatile(
        "mma.sync.aligned.m16n8k16.row.col.f32.bf16.bf16.f32 "
        "{%0,%1,%2,%3},{%4,%5,%6,%7},{%8,%9},{%0,%1,%2,%3};"
        : "+f"(c[0]), "+f"(c[1]), "+f"(c[2]), "+f"(c[3])
        : "r"(a[0]), "r"(a[1]), "r"(a[2]), "r"(a[3]), "r"(b[0]), "r"(b[1]));
}

// ============================ split fp32 -> bf16 hi/lo ============================
__global__ __launch_bounds__(256) void split_kernel(
    const float* __restrict__ src, __nv_bfloat16* __restrict__ hi,
    __nv_bfloat16* __restrict__ lo, int n)
{
    int i = (blockIdx.x * blockDim.x + threadIdx.x) * 4;
    if (i < n) {
        float4 v = *(const float4*)(src + i);
        float vv[4] = {v.x, v.y, v.z, v.w};
        uint32_t hp[2], lp[2];
        unsigned short hb[4], lb[4];
#pragma unroll
        for (int e = 0; e < 4; e++) {
            __nv_bfloat16 h = __float2bfloat16(vv[e]);
            float r = vv[e] - __bfloat162float(h);
            hb[e] = __bfloat16_as_ushort(h);
            lb[e] = __bfloat16_as_ushort(__float2bfloat16(r));
        }
        hp[0] = (uint32_t)hb[0] | ((uint32_t)hb[1] << 16);
        hp[1] = (uint32_t)hb[2] | ((uint32_t)hb[3] << 16);
        lp[0] = (uint32_t)lb[0] | ((uint32_t)lb[1] << 16);
        lp[1] = (uint32_t)lb[2] | ((uint32_t)lb[3] << 16);
        *(uint2*)(hi + i) = make_uint2(hp[0], hp[1]);
        *(uint2*)(lo + i) = make_uint2(lp[0], lp[1]);
    }
}

// ============================ bf16x3 mma.sync GEMM ============================
// C[BM,BN] tile of A @ B^T.  A:[M,K] hi/lo bf16 row-major, B:[N,K] hi/lo bf16 row-major.
// MODE 0: GEMM1 — gate tiles (bn<DD): outF = sigmoid(acc) (u);
//                 value tiles: (ohi,olo) = bf16 hi/lo split of acc (vx).
// MODE 1: GEMM2 — outF = acc (cand).
template <int MODE>
__global__ __launch_bounds__(256, 1)
void gemm_mma(const __nv_bfloat16* __restrict__ Ahi, const __nv_bfloat16* __restrict__ Alo,
              const __nv_bfloat16* __restrict__ Bhi, const __nv_bfloat16* __restrict__ Blo,
              float* __restrict__ outF,
              __nv_bfloat16* __restrict__ ohi, __nv_bfloat16* __restrict__ olo,
              int ntn)
{
    extern __shared__ char smem[];
    const uint32_t sb = smem_u32(smem);
    const int tid = threadIdx.x;
    const int wid = tid >> 5, lane = tid & 31;

    // CTA swizzle: GROUP_M m-tiles per n-sweep for L2 reuse
    int per_group = GROUP_M * ntn;
    int group = blockIdx.x / per_group;
    int rem = blockIdx.x % per_group;
    const int bm = (group * GROUP_M + (rem % GROUP_M)) * BM;
    const int bn = (rem / GROUP_M) * BN;

    const int wm = wid & 1;   // 2 m-slices of 64
    const int wn = wid >> 1;  // 4 n-slices of 32

    // per-thread ldmatrix smem offsets (stage-invariant)
    uint32_t offA[4], offB[2];
#pragma unroll
    for (int mf = 0; mf < 4; mf++)
        offA[mf] = (uint32_t)(wm * 64 + mf * 16 + (lane & 15)) * ROWB + (lane >> 4) * 16;
#pragma unroll
    for (int p = 0; p < 2; p++)
        offB[p] = (uint32_t)(wn * 32 + p * 16 + ((lane >> 4) & 1) * 8 + (lane & 7)) * ROWB
                  + ((lane >> 3) & 1) * 16;

    float acc[4][4][4];
#pragma unroll
    for (int a = 0; a < 4; a++)
#pragma unroll
        for (int b = 0; b < 4; b++)
#pragma unroll
            for (int e = 0; e < 4; e++) acc[a][b][e] = 0.f;

    auto load_stage = [&](int kc) {
        uint32_t base = sb + (uint32_t)(kc % NSTAGE) * STAGE_B;
        int k0 = kc * BK;
#pragma unroll
        for (int j = 0; j < 2; j++) {
            int ch = tid + j * 256;           // 512 16B-chunks per matrix
            int row = ch >> 2, kc4 = ch & 3;
            uint32_t doff = (uint32_t)row * ROWB + kc4 * 16;
            size_t ga = (size_t)(bm + row) * DD + k0 + kc4 * 8;
            size_t gb = (size_t)(bn + row) * DD + k0 + kc4 * 8;
            cp16(base + A_HI_OFF + doff, Ahi + ga);
            cp16(base + A_LO_OFF + doff, Alo + ga);
            cp16(base + B_HI_OFF + doff, Bhi + gb);
            cp16(base + B_LO_OFF + doff, Blo + gb);
        }
        cp_commit();
    };

    load_stage(0);
    load_stage(1);

    const int NKC = DD / BK;   // 32
    for (int kc = 0; kc < NKC; kc++) {
        cp_wait<1>();
        __syncthreads();                     // stage kc visible; prev compute done
        if (kc + 2 < NKC) load_stage(kc + 2);

        uint32_t base = sb + (uint32_t)(kc % NSTAGE) * STAGE_B;
#pragma unroll
        for (int kk = 0; kk < 2; kk++) {
            uint32_t ah[4][4], al[4][4], bhv[2][4], blv[2][4];
#pragma unroll
            for (int mf = 0; mf < 4; mf++) {
                ldsm4(ah[mf], base + A_HI_OFF + offA[mf] + kk * 32);
                ldsm4(al[mf], base + A_LO_OFF + offA[mf] + kk * 32);
            }
#pragma unroll
            for (int p = 0; p < 2; p++) {
                ldsm4(bhv[p], base + B_HI_OFF + offB[p] + kk * 32);
                ldsm4(blv[p], base + B_LO_OFF + offB[p] + kk * 32);
            }
#pragma unroll
            for (int mf = 0; mf < 4; mf++) {
#pragma unroll
                for (int nf = 0; nf < 4; nf++) {
                    const uint32_t* bh2 = &bhv[nf >> 1][(nf & 1) * 2];
                    const uint32_t* bl2 = &blv[nf >> 1][(nf & 1) * 2];
                    mma16816(acc[mf][nf], ah[mf], bh2);   // hi*hi
                    mma16816(acc[mf][nf], al[mf], bh2);   // lo*hi
                    mma16816(acc[mf][nf], ah[mf], bl2);   // hi*lo
                }
            }
        }
    }

    // ---- epilogue ----
    const int r0 = bm + wm * 64 + (lane >> 2);
    const int c0 = bn + wn * 32 + (lane & 3) * 2;
    const bool gate = (MODE == 0) && (bn < DD);

#pragma unroll
    for (int mf = 0; mf < 4; mf++) {
        int r = r0 + mf * 16;
#pragma unroll
        for (int nf = 0; nf < 4; nf++) {
            int c = c0 + nf * 8;
            float* a = acc[mf][nf];
            if (MODE == 1) {
                *(float2*)(outF + (size_t)r * DD + c)       = make_float2(a[0], a[1]);
                *(float2*)(outF + (size_t)(r + 8) * DD + c) = make_float2(a[2], a[3]);
            } else if (gate) {
                float2 s0, s1;
                s0.x = 1.f / (1.f + __expf(-a[0]));
                s0.y = 1.f / (1.f + __expf(-a[1]));
                s1.x = 1.f / (1.f + __expf(-a[2]));
                s1.y = 1.f / (1.f + __expf(-a[3]));
                *(float2*)(outF + (size_t)r * DD + c)       = s0;
                *(float2*)(outF + (size_t)(r + 8) * DD + c) = s1;
            } else {
                int cc = c - DD;
                unsigned short hb[4], lb[4];
#pragma unroll
                for (int e = 0; e < 4; e++) {
                    __nv_bfloat16 h = __float2bfloat16(a[e]);
                    float rr = a[e] - __bfloat162float(h);
                    hb[e] = __bfloat16_as_ushort(h);
                    lb[e] = __bfloat16_as_ushort(__float2bfloat16(rr));
                }
                *(uint32_t*)(ohi + (size_t)r * DD + cc)       = (uint32_t)hb[0] | ((uint32_t)hb[1] << 16);
                *(uint32_t*)(ohi + (size_t)(r + 8) * DD + cc) = (uint32_t)hb[2] | ((uint32_t)hb[3] << 16);
                *(uint32_t*)(olo + (size_t)r * DD + cc)       = (uint32_t)lb[0] | ((uint32_t)lb[1] << 16);
                *(uint32_t*)(olo + (size_t)(r + 8) * DD + cc) = (uint32_t)lb[2] | ((uint32_t)lb[3] << 16);
            }
        }
    }
}

// ============================ scan (diagonal recurrence) ============================
// h_t = u*h + (1-u)*c = fma(u, h-c, c). Reads g_u, g_c; writes y in-place into g_c.
__global__ __launch_bounds__(256) void scan_kernel()
{
    int idx = blockIdx.x * blockDim.x + threadIdx.x;   // 0 .. B*D-1
    int b = idx >> 10;
    int d = idx & (DD - 1);
    float* up = g_u + (size_t)b * TT * DD + d;
    float* cp = g_c + (size_t)b * TT * DD + d;
    float h = 0.f;
    for (int t = 0; t < TT; t += 8) {
        float uu[8], cc[8];
#pragma unroll
        for (int j = 0; j < 8; j++) {
            uu[j] = up[(size_t)(t + j) * DD];
            cc[j] = cp[(size_t)(t + j) * DD];
        }
#pragma unroll
        for (int j = 0; j < 8; j++) {
            h = fmaf(uu[j], h - cc[j], cc[j]);
            cc[j] = h;
        }
#pragma unroll
        for (int j = 0; j < 8; j++) cp[(size_t)(t + j) * DD] = cc[j];
    }
}

// ============================ LayerNorm ============================
__global__ __launch_bounds__(256) void ln_kernel(const float* __restrict__ gamma,
                                                 const float* __restrict__ beta,
                                                 float* __restrict__ out)
{
    int row = blockIdx.x;
    int t = threadIdx.x;
    const float4* yr = (const float4*)(g_c + (size_t)row * DD);
    float4 v = yr[t];
    float s = v.x + v.y + v.z + v.w;
    float q = v.x * v.x + v.y * v.y + v.z * v.z + v.w * v.w;

#pragma unroll
    for (int o = 16; o; o >>= 1) {
        s += __shfl_xor_sync(0xFFFFFFFFu, s, o);
        q += __shfl_xor_sync(0xFFFFFFFFu, q, o);
    }
    __shared__ float sw[8], qw[8];
    __shared__ float mu_s, inv_s;
    int w = t >> 5, l = t & 31;
    if (l == 0) { sw[w] = s; qw[w] = q; }
    __syncthreads();
    if (t == 0) {
        float S = 0.f, Q = 0.f;
#pragma unroll
        for (int i = 0; i < 8; i++) { S += sw[i]; Q += qw[i]; }
        float mu = S * (1.f / DD);
        float var = Q * (1.f / DD) - mu * mu;
        mu_s = mu;
        inv_s = rsqrtf(var + LN_EPS);
    }
    __syncthreads();
    float mu = mu_s, inv = inv_s;

    const float4* g4 = (const float4*)gamma;
    const float4* b4 = (const float4*)beta;
    float4 gv = g4[t], bv = b4[t];
    float4 o;
    o.x = (v.x - mu) * inv * gv.x + bv.x;
    o.y = (v.y - mu) * inv * gv.y + bv.y;
    o.z = (v.z - mu) * inv * gv.z + bv.z;
    o.w = (v.w - mu) * inv * gv.w + bv.w;
    ((float4*)(out + (size_t)row * DD))[t] = o;
}

// ============================ host ============================
extern "C" void kernel_launch(void* const* d_in, const int* in_sizes, int n_in,
                              void* d_out, int out_size)
{
    const float* x       = (const float*)d_in[0];
    const float* W_in    = (const float*)d_in[1];
    const float* W_state = (const float*)d_in[2];
    const float* gamma   = (const float*)d_in[3];
    const float* beta    = (const float*)d_in[4];
    float* out = (float*)d_out;

    void *pxh, *pxl, *pwh, *pwl, *psh, *psl, *pvh, *pvl, *pu, *pc;
    cudaGetSymbolAddress(&pxh, g_xhi); cudaGetSymbolAddress(&pxl, g_xlo);
    cudaGetSymbolAddress(&pwh, g_whi); cudaGetSymbolAddress(&pwl, g_wlo);
    cudaGetSymbolAddress(&psh, g_shi); cudaGetSymbolAddress(&psl, g_slo);
    cudaGetSymbolAddress(&pvh, g_vhi); cudaGetSymbolAddress(&pvl, g_vlo);
    cudaGetSymbolAddress(&pu,  g_u);   cudaGetSymbolAddress(&pc,  g_c);

    cudaFuncSetAttribute(gemm_mma<0>, cudaFuncAttributeMaxDynamicSharedMemorySize, SMEM_TOTAL);
    cudaFuncSetAttribute(gemm_mma<1>, cudaFuncAttributeMaxDynamicSharedMemorySize, SMEM_TOTAL);

    // fp32 -> bf16 hi/lo splits
    { int n = MROWS * DD;  split_kernel<<<(n / 4 + 255) / 256, 256>>>(x, (__nv_bfloat16*)pxh, (__nv_bfloat16*)pxl, n); }
    { int n = 2 * DD * DD; split_kernel<<<(n / 4 + 255) / 256, 256>>>(W_in, (__nv_bfloat16*)pwh, (__nv_bfloat16*)pwl, n); }
    { int n = DD * DD;     split_kernel<<<(n / 4 + 255) / 256, 256>>>(W_state, (__nv_bfloat16*)psh, (__nv_bfloat16*)psl, n); }

    // GEMM1: [32768,1024] @ [2048,1024]^T -> u (sigmoid fp32) + vx (bf16 hi/lo)
    {
        int ntm = MROWS / BM, ntn = 2 * DD / BN;   // 256, 16
        gemm_mma<0><<<ntm * ntn, 256, SMEM_TOTAL>>>(
            (const __nv_bfloat16*)pxh, (const __nv_bfloat16*)pxl,
            (const __nv_bfloat16*)pwh, (const __nv_bfloat16*)pwl,
            (float*)pu, (__nv_bfloat16*)pvh, (__nv_bfloat16*)pvl, ntn);
    }
    // GEMM2: [32768,1024] @ [1024,1024]^T -> cand (fp32)
    {
        int ntm = MROWS / BM, ntn = DD / BN;       // 256, 8
        gemm_mma<1><<<ntm * ntn, 256, SMEM_TOTAL>>>(
            (const __nv_bfloat16*)pvh, (const __nv_bfloat16*)pvl,
            (const __nv_bfloat16*)psh, (const __nv_bfloat16*)psl,
            (float*)pc, nullptr, nullptr, ntn);
    }

    // scan over T (y written in-place into g_c), then LN
    scan_kernel<<<(BB * DD) / 256, 256>>>();
    ln_kernel<<<MROWS, 256>>>(gamma, beta, out);
}

// round 4
// speedup vs baseline: 2.7438x; 1.1150x over previous
#include <cuda_runtime.h>
#include <cuda_bf16.h>
#include <math.h>
#include <stdint.h>

#define BB 16
#define TT 2048
#define DD 1024
#define MROWS (BB * TT)       // 32768
#define LN_EPS 1e-5f

// ---- GEMM tiling ----
#define BM 256
#define BN 128
#define BK 32                  // bf16 elems per k-chunk
#define NSTAGE 3
#define NTHREADS 512
#define ROWB 80                // padded smem row: 64B data + 16B pad (conflict-free ldmatrix)
#define A_HI_OFF 0
#define A_LO_OFF (BM * ROWB)                     // 20480
#define B_HI_OFF (2 * BM * ROWB)                 // 40960
#define B_LO_OFF (2 * BM * ROWB + BN * ROWB)     // 51200
#define STAGE_B  (2 * BM * ROWB + 2 * BN * ROWB) // 61440
#define SMEM_TOTAL (NSTAGE * STAGE_B)            // 184320
#define GROUP_M 8

// ---- scratch (__device__ globals; no cudaMalloc allowed) ----
__device__ __nv_bfloat16 g_xhi[(size_t)MROWS * DD];
__device__ __nv_bfloat16 g_xlo[(size_t)MROWS * DD];
__device__ __nv_bfloat16 g_whi[(size_t)2 * DD * DD];
__device__ __nv_bfloat16 g_wlo[(size_t)2 * DD * DD];
__device__ __nv_bfloat16 g_shi[(size_t)DD * DD];
__device__ __nv_bfloat16 g_slo[(size_t)DD * DD];
__device__ __nv_bfloat16 g_vhi[(size_t)MROWS * DD];
__device__ __nv_bfloat16 g_vlo[(size_t)MROWS * DD];
__device__ float g_u[(size_t)MROWS * DD];
__device__ float g_c[(size_t)MROWS * DD];

// ============================ device helpers ============================
__device__ __forceinline__ uint32_t smem_u32(const void* p) {
    uint32_t a;
    asm("{ .reg .u64 t; cvta.to.shared.u64 t, %1; cvt.u32.u64 %0, t; }" : "=r"(a) : "l"(p));
    return a;
}
__device__ __forceinline__ void cp16(uint32_t dst, const void* src) {
    asm volatile("cp.async.cg.shared.global [%0], [%1], 16;" :: "r"(dst), "l"(src));
}
__device__ __forceinline__ void cp_commit() {
    asm volatile("cp.async.commit_group;" ::: "memory");
}
template <int N>
__device__ __forceinline__ void cp_wait() {
    asm volatile("cp.async.wait_group %0;" :: "n"(N) : "memory");
}
__device__ __forceinline__ void ldsm4(uint32_t* r, uint32_t a) {
    asm volatile("ldmatrix.sync.aligned.m8n8.x4.shared.b16 {%0,%1,%2,%3}, [%4];"
                 : "=r"(r[0]), "=r"(r[1]), "=r"(r[2]), "=r"(r[3]) : "r"(a));
}
__device__ __forceinline__ void mma16816(float* c, const uint32_t* a, const uint32_t* b) {
    asm volatile(
        "mma.sync.aligned.m16n8k16.row.col.f32.bf16.bf16.f32 "
        "{%0,%1,%2,%3},{%4,%5,%6,%7},{%8,%9},{%0,%1,%2,%3};"
        : "+f"(c[0]), "+f"(c[1]), "+f"(c[2]), "+f"(c[3])
        : "r"(a[0]), "r"(a[1]), "r"(a[2]), "r"(a[3]), "r"(b[0]), "r"(b[1]));
}

// ============================ split fp32 -> bf16 hi/lo ============================
__global__ __launch_bounds__(256) void split_kernel(
    const float* __restrict__ src, __nv_bfloat16* __restrict__ hi,
    __nv_bfloat16* __restrict__ lo, int n)
{
    int i = (blockIdx.x * blockDim.x + threadIdx.x) * 4;
    if (i < n) {
        float4 v = *(const float4*)(src + i);
        float vv[4] = {v.x, v.y, v.z, v.w};
        unsigned short hb[4], lb[4];
#pragma unroll
        for (int e = 0; e < 4; e++) {
            __nv_bfloat16 h = __float2bfloat16(vv[e]);
            float r = vv[e] - __bfloat162float(h);
            hb[e] = __bfloat16_as_ushort(h);
            lb[e] = __bfloat16_as_ushort(__float2bfloat16(r));
        }
        *(uint2*)(hi + i) = make_uint2((uint32_t)hb[0] | ((uint32_t)hb[1] << 16),
                                       (uint32_t)hb[2] | ((uint32_t)hb[3] << 16));
        *(uint2*)(lo + i) = make_uint2((uint32_t)lb[0] | ((uint32_t)lb[1] << 16),
                                       (uint32_t)lb[2] | ((uint32_t)lb[3] << 16));
    }
}

// ============================ bf16x3 mma.sync GEMM ============================
// C[BM,BN] tile of A @ B^T.  A:[M,K] hi/lo bf16 row-major, B:[N,K] hi/lo bf16 row-major.
// 512 threads: 16 warps = 4 m-slices (64) x 4 n-slices (32).
// MODE 0: GEMM1 — gate tiles (bn<DD): outF = sigmoid(acc) (u);
//                 value tiles: (ohi,olo) = bf16 hi/lo split of acc (vx).
// MODE 1: GEMM2 — outF = acc (cand).
template <int MODE>
__global__ __launch_bounds__(NTHREADS, 1)
void gemm_mma(const __nv_bfloat16* __restrict__ Ahi, const __nv_bfloat16* __restrict__ Alo,
              const __nv_bfloat16* __restrict__ Bhi, const __nv_bfloat16* __restrict__ Blo,
              float* __restrict__ outF,
              __nv_bfloat16* __restrict__ ohi, __nv_bfloat16* __restrict__ olo,
              int ntn)
{
    extern __shared__ char smem[];
    const uint32_t sb = smem_u32(smem);
    const int tid = threadIdx.x;
    const int wid = tid >> 5, lane = tid & 31;

    // CTA swizzle: GROUP_M m-tiles per n-sweep for L2 reuse
    int per_group = GROUP_M * ntn;
    int group = blockIdx.x / per_group;
    int rem = blockIdx.x % per_group;
    const int bm = (group * GROUP_M + (rem % GROUP_M)) * BM;
    const int bn = (rem / GROUP_M) * BN;

    const int wm = wid & 3;   // 4 m-slices of 64
    const int wn = wid >> 2;  // 4 n-slices of 32

    // per-thread ldmatrix smem offsets (stage-invariant)
    uint32_t offA[4], offB[2];
#pragma unroll
    for (int mf = 0; mf < 4; mf++)
        offA[mf] = (uint32_t)(wm * 64 + mf * 16 + (lane & 15)) * ROWB + (lane >> 4) * 16;
#pragma unroll
    for (int p = 0; p < 2; p++)
        offB[p] = (uint32_t)(wn * 32 + p * 16 + ((lane >> 4) & 1) * 8 + (lane & 7)) * ROWB
                  + ((lane >> 3) & 1) * 16;

    float acc[4][4][4];
#pragma unroll
    for (int a = 0; a < 4; a++)
#pragma unroll
        for (int b = 0; b < 4; b++)
#pragma unroll
            for (int e = 0; e < 4; e++) acc[a][b][e] = 0.f;

    auto load_stage = [&](int kc) {
        uint32_t base = sb + (uint32_t)(kc % NSTAGE) * STAGE_B;
        int k0 = kc * BK;
        // A: BM*BK*2B = 16384B = 1024 16B-chunks per matrix (2 per thread)
#pragma unroll
        for (int j = 0; j < 2; j++) {
            int ch = tid + j * NTHREADS;
            int row = ch >> 2, kc4 = ch & 3;
            uint32_t doff = (uint32_t)row * ROWB + kc4 * 16;
            size_t ga = (size_t)(bm + row) * DD + k0 + kc4 * 8;
            cp16(base + A_HI_OFF + doff, Ahi + ga);
            cp16(base + A_LO_OFF + doff, Alo + ga);
        }
        // B: BN*BK*2B = 8192B = 512 chunks per matrix (1 per thread)
        {
            int row = tid >> 2, kc4 = tid & 3;
            uint32_t doff = (uint32_t)row * ROWB + kc4 * 16;
            size_t gb = (size_t)(bn + row) * DD + k0 + kc4 * 8;
            cp16(base + B_HI_OFF + doff, Bhi + gb);
            cp16(base + B_LO_OFF + doff, Blo + gb);
        }
        cp_commit();
    };

    load_stage(0);
    load_stage(1);

    const int NKC = DD / BK;   // 32
    for (int kc = 0; kc < NKC; kc++) {
        cp_wait<1>();
        __syncthreads();                     // stage kc visible; prev compute done
        if (kc + 2 < NKC) load_stage(kc + 2);

        uint32_t base = sb + (uint32_t)(kc % NSTAGE) * STAGE_B;
#pragma unroll
        for (int kk = 0; kk < 2; kk++) {
            uint32_t ah[4][4], al[4][4], bv[2][4];
#pragma unroll
            for (int mf = 0; mf < 4; mf++) {
                ldsm4(ah[mf], base + A_HI_OFF + offA[mf] + kk * 32);
                ldsm4(al[mf], base + A_LO_OFF + offA[mf] + kk * 32);
            }
            // pass 1: B_hi  (hi*hi and lo*hi)
#pragma unroll
            for (int p = 0; p < 2; p++) ldsm4(bv[p], base + B_HI_OFF + offB[p] + kk * 32);
#pragma unroll
            for (int mf = 0; mf < 4; mf++) {
#pragma unroll
                for (int nf = 0; nf < 4; nf++) {
                    const uint32_t* b2 = &bv[nf >> 1][(nf & 1) * 2];
                    mma16816(acc[mf][nf], ah[mf], b2);
                    mma16816(acc[mf][nf], al[mf], b2);
                }
            }
            // pass 2: B_lo  (hi*lo), reuse bv registers
#pragma unroll
            for (int p = 0; p < 2; p++) ldsm4(bv[p], base + B_LO_OFF + offB[p] + kk * 32);
#pragma unroll
            for (int mf = 0; mf < 4; mf++) {
#pragma unroll
                for (int nf = 0; nf < 4; nf++) {
                    const uint32_t* b2 = &bv[nf >> 1][(nf & 1) * 2];
                    mma16816(acc[mf][nf], ah[mf], b2);
                }
            }
        }
    }

    // ---- epilogue ----
    const int r0 = bm + wm * 64 + (lane >> 2);
    const int c0 = bn + wn * 32 + (lane & 3) * 2;
    const bool gate = (MODE == 0) && (bn < DD);

#pragma unroll
    for (int mf = 0; mf < 4; mf++) {
        int r = r0 + mf * 16;
#pragma unroll
        for (int nf = 0; nf < 4; nf++) {
            int c = c0 + nf * 8;
            float* a = acc[mf][nf];
            if (MODE == 1) {
                *(float2*)(outF + (size_t)r * DD + c)       = make_float2(a[0], a[1]);
                *(float2*)(outF + (size_t)(r + 8) * DD + c) = make_float2(a[2], a[3]);
            } else if (gate) {
                float2 s0, s1;
                s0.x = 1.f / (1.f + __expf(-a[0]));
                s0.y = 1.f / (1.f + __expf(-a[1]));
                s1.x = 1.f / (1.f + __expf(-a[2]));
                s1.y = 1.f / (1.f + __expf(-a[3]));
                *(float2*)(outF + (size_t)r * DD + c)       = s0;
                *(float2*)(outF + (size_t)(r + 8) * DD + c) = s1;
            } else {
                int cc = c - DD;
                unsigned short hb[4], lb[4];
#pragma unroll
                for (int e = 0; e < 4; e++) {
                    __nv_bfloat16 h = __float2bfloat16(a[e]);
                    float rr = a[e] - __bfloat162float(h);
                    hb[e] = __bfloat16_as_ushort(h);
                    lb[e] = __bfloat16_as_ushort(__float2bfloat16(rr));
                }
                *(uint32_t*)(ohi + (size_t)r * DD + cc)       = (uint32_t)hb[0] | ((uint32_t)hb[1] << 16);
                *(uint32_t*)(ohi + (size_t)(r + 8) * DD + cc) = (uint32_t)hb[2] | ((uint32_t)hb[3] << 16);
                *(uint32_t*)(olo + (size_t)r * DD + cc)       = (uint32_t)lb[0] | ((uint32_t)lb[1] << 16);
                *(uint32_t*)(olo + (size_t)(r + 8) * DD + cc) = (uint32_t)lb[2] | ((uint32_t)lb[3] << 16);
            }
        }
    }
}

// ============================ scan (diagonal recurrence) ============================
// h_t = u*h + (1-u)*c = fma(u, h-c, c). Reads g_u, g_c; writes y in-place into g_c.
__global__ __launch_bounds__(256) void scan_kernel()
{
    int idx = blockIdx.x * blockDim.x + threadIdx.x;   // 0 .. B*D-1
    int b = idx >> 10;
    int d = idx & (DD - 1);
    float* up = g_u + (size_t)b * TT * DD + d;
    float* cp = g_c + (size_t)b * TT * DD + d;
    float h = 0.f;
    for (int t = 0; t < TT; t += 8) {
        float uu[8], cc[8];
#pragma unroll
        for (int j = 0; j < 8; j++) {
            uu[j] = up[(size_t)(t + j) * DD];
            cc[j] = cp[(size_t)(t + j) * DD];
        }
#pragma unroll
        for (int j = 0; j < 8; j++) {
            h = fmaf(uu[j], h - cc[j], cc[j]);
            cc[j] = h;
        }
#pragma unroll
        for (int j = 0; j < 8; j++) cp[(size_t)(t + j) * DD] = cc[j];
    }
}

// ============================ LayerNorm ============================
__global__ __launch_bounds__(256) void ln_kernel(const float* __restrict__ gamma,
                                                 const float* __restrict__ beta,
                                                 float* __restrict__ out)
{
    int row = blockIdx.x;
    int t = threadIdx.x;
    const float4* yr = (const float4*)(g_c + (size_t)row * DD);
    float4 v = yr[t];
    float s = v.x + v.y + v.z + v.w;
    float q = v.x * v.x + v.y * v.y + v.z * v.z + v.w * v.w;

#pragma unroll
    for (int o = 16; o; o >>= 1) {
        s += __shfl_xor_sync(0xFFFFFFFFu, s, o);
        q += __shfl_xor_sync(0xFFFFFFFFu, q, o);
    }
    __shared__ float sw[8], qw[8];
    __shared__ float mu_s, inv_s;
    int w = t >> 5, l = t & 31;
    if (l == 0) { sw[w] = s; qw[w] = q; }
    __syncthreads();
    if (t == 0) {
        float S = 0.f, Q = 0.f;
#pragma unroll
        for (int i = 0; i < 8; i++) { S += sw[i]; Q += qw[i]; }
        float mu = S * (1.f / DD);
        float var = Q * (1.f / DD) - mu * mu;
        mu_s = mu;
        inv_s = rsqrtf(var + LN_EPS);
    }
    __syncthreads();
    float mu = mu_s, inv = inv_s;

    const float4* g4 = (const float4*)gamma;
    const float4* b4 = (const float4*)beta;
    float4 gv = g4[t], bv = b4[t];
    float4 o;
    o.x = (v.x - mu) * inv * gv.x + bv.x;
    o.y = (v.y - mu) * inv * gv.y + bv.y;
    o.z = (v.z - mu) * inv * gv.z + bv.z;
    o.w = (v.w - mu) * inv * gv.w + bv.w;
    ((float4*)(out + (size_t)row * DD))[t] = o;
}

// ============================ host ============================
extern "C" void kernel_launch(void* const* d_in, const int* in_sizes, int n_in,
                              void* d_out, int out_size)
{
    const float* x       = (const float*)d_in[0];
    const float* W_in    = (const float*)d_in[1];
    const float* W_state = (const float*)d_in[2];
    const float* gamma   = (const float*)d_in[3];
    const float* beta    = (const float*)d_in[4];
    float* out = (float*)d_out;

    void *pxh, *pxl, *pwh, *pwl, *psh, *psl, *pvh, *pvl, *pu, *pc;
    cudaGetSymbolAddress(&pxh, g_xhi); cudaGetSymbolAddress(&pxl, g_xlo);
    cudaGetSymbolAddress(&pwh, g_whi); cudaGetSymbolAddress(&pwl, g_wlo);
    cudaGetSymbolAddress(&psh, g_shi); cudaGetSymbolAddress(&psl, g_slo);
    cudaGetSymbolAddress(&pvh, g_vhi); cudaGetSymbolAddress(&pvl, g_vlo);
    cudaGetSymbolAddress(&pu,  g_u);   cudaGetSymbolAddress(&pc,  g_c);

    cudaFuncSetAttribute(gemm_mma<0>, cudaFuncAttributeMaxDynamicSharedMemorySize, SMEM_TOTAL);
    cudaFuncSetAttribute(gemm_mma<1>, cudaFuncAttributeMaxDynamicSharedMemorySize, SMEM_TOTAL);

    // fp32 -> bf16 hi/lo splits
    { int n = MROWS * DD;  split_kernel<<<(n / 4 + 255) / 256, 256>>>(x, (__nv_bfloat16*)pxh, (__nv_bfloat16*)pxl, n); }
    { int n = 2 * DD * DD; split_kernel<<<(n / 4 + 255) / 256, 256>>>(W_in, (__nv_bfloat16*)pwh, (__nv_bfloat16*)pwl, n); }
    { int n = DD * DD;     split_kernel<<<(n / 4 + 255) / 256, 256>>>(W_state, (__nv_bfloat16*)psh, (__nv_bfloat16*)psl, n); }

    // GEMM1: [32768,1024] @ [2048,1024]^T -> u (sigmoid fp32) + vx (bf16 hi/lo)
    {
        int ntm = MROWS / BM, ntn = 2 * DD / BN;   // 128, 16
        gemm_mma<0><<<ntm * ntn, NTHREADS, SMEM_TOTAL>>>(
            (const __nv_bfloat16*)pxh, (const __nv_bfloat16*)pxl,
            (const __nv_bfloat16*)pwh, (const __nv_bfloat16*)pwl,
            (float*)pu, (__nv_bfloat16*)pvh, (__nv_bfloat16*)pvl, ntn);
    }
    // GEMM2: [32768,1024] @ [1024,1024]^T -> cand (fp32)
    {
        int ntm = MROWS / BM, ntn = DD / BN;       // 128, 8
        gemm_mma<1><<<ntm * ntn, NTHREADS, SMEM_TOTAL>>>(
            (const __nv_bfloat16*)pvh, (const __nv_bfloat16*)pvl,
            (const __nv_bfloat16*)psh, (const __nv_bfloat16*)psl,
            (float*)pc, nullptr, nullptr, ntn);
    }

    // scan over T (y written in-place into g_c), then LN
    scan_kernel<<<(BB * DD) / 256, 256>>>();
    ln_kernel<<<MROWS, 256>>>(gamma, beta, out);
}

// round 5
// speedup vs baseline: 3.1713x; 1.1558x over previous
#include <cuda_runtime.h>
#include <cuda_bf16.h>
#include <math.h>
#include <stdint.h>

#define BB 16
#define TT 2048
#define DD 1024
#define MROWS (BB * TT)       // 32768
#define LN_EPS 1e-5f

// ---- GEMM tiling ----
#define BM 256
#define BN 128
#define BK 32                  // bf16 elems per k-chunk
#define NSTAGE 4
#define NTHREADS 512
#define ROWB 80                // padded smem row: 64B data + 16B pad (conflict-free ldmatrix)
#define A_HI_OFF 0
#define A_LO_OFF (BM * ROWB)                     // 20480
#define B_HI_OFF (2 * BM * ROWB)                 // 40960
#define B_LO_OFF (2 * BM * ROWB + BN * ROWB)     // 51200
#define STAGE_B  (2 * BM * ROWB + 2 * BN * ROWB) // 61440
#define SMEM_TOTAL (NSTAGE * STAGE_B)            // 245760? no: 4*61440 = 245760 > 227KB!
// NOTE: 4 * 61440 = 245760 exceeds the 227KB limit. Use A-lo/B-lo packed tighter:
// Instead keep NSTAGE=4 but drop per-stage pad waste by using ROWB=72? ldmatrix needs 16B align.
// Fallback: NSTAGE=3 for A (hi+lo) is required; instead we shrink to NSTAGE_EFF below.
#undef SMEM_TOTAL
#define SMEM_TOTAL (NSTAGE * STAGE_B > 232448 ? 3 * STAGE_B : NSTAGE * STAGE_B)
#define GROUP_M 8

// ---- scratch (__device__ globals; no cudaMalloc allowed) ----
__device__ __nv_bfloat16 g_xhi[(size_t)MROWS * DD];
__device__ __nv_bfloat16 g_xlo[(size_t)MROWS * DD];
__device__ __nv_bfloat16 g_whi[(size_t)2 * DD * DD];
__device__ __nv_bfloat16 g_wlo[(size_t)2 * DD * DD];
__device__ __nv_bfloat16 g_shi[(size_t)DD * DD];
__device__ __nv_bfloat16 g_slo[(size_t)DD * DD];
__device__ __nv_bfloat16 g_vhi[(size_t)MROWS * DD];
__device__ __nv_bfloat16 g_vlo[(size_t)MROWS * DD];
__device__ float g_u[(size_t)MROWS * DD];
__device__ float g_c[(size_t)MROWS * DD];

// ============================ device helpers ============================
__device__ __forceinline__ uint32_t smem_u32(const void* p) {
    uint32_t a;
    asm("{ .reg .u64 t; cvta.to.shared.u64 t, %1; cvt.u32.u64 %0, t; }" : "=r"(a) : "l"(p));
    return a;
}
__device__ __forceinline__ void cp16(uint32_t dst, const void* src) {
    asm volatile("cp.async.cg.shared.global [%0], [%1], 16;" :: "r"(dst), "l"(src));
}
__device__ __forceinline__ void cp_commit() {
    asm volatile("cp.async.commit_group;" ::: "memory");
}
template <int N>
__device__ __forceinline__ void cp_wait() {
    asm volatile("cp.async.wait_group %0;" :: "n"(N) : "memory");
}
__device__ __forceinline__ void ldsm4(uint32_t* r, uint32_t a) {
    asm volatile("ldmatrix.sync.aligned.m8n8.x4.shared.b16 {%0,%1,%2,%3}, [%4];"
                 : "=r"(r[0]), "=r"(r[1]), "=r"(r[2]), "=r"(r[3]) : "r"(a));
}
__device__ __forceinline__ void mma16816(float* c, const uint32_t* a, const uint32_t* b) {
    asm volatile(
        "mma.sync.aligned.m16n8k16.row.col.f32.bf16.bf16.f32 "
        "{%0,%1,%2,%3},{%4,%5,%6,%7},{%8,%9},{%0,%1,%2,%3};"
        : "+f"(c[0]), "+f"(c[1]), "+f"(c[2]), "+f"(c[3])
        : "r"(a[0]), "r"(a[1]), "r"(a[2]), "r"(a[3]), "r"(b[0]), "r"(b[1]));
}

// ============================ split fp32 -> bf16 hi/lo ============================
__global__ __launch_bounds__(256) void split_kernel(
    const float* __restrict__ src, __nv_bfloat16* __restrict__ hi,
    __nv_bfloat16* __restrict__ lo, int n)
{
    int i = (blockIdx.x * blockDim.x + threadIdx.x) * 4;
    if (i < n) {
        float4 v = *(const float4*)(src + i);
        float vv[4] = {v.x, v.y, v.z, v.w};
        unsigned short hb[4], lb[4];
#pragma unroll
        for (int e = 0; e < 4; e++) {
            __nv_bfloat16 h = __float2bfloat16(vv[e]);
            float r = vv[e] - __bfloat162float(h);
            hb[e] = __bfloat16_as_ushort(h);
            lb[e] = __bfloat16_as_ushort(__float2bfloat16(r));
        }
        *(uint2*)(hi + i) = make_uint2((uint32_t)hb[0] | ((uint32_t)hb[1] << 16),
                                       (uint32_t)hb[2] | ((uint32_t)hb[3] << 16));
        *(uint2*)(lo + i) = make_uint2((uint32_t)lb[0] | ((uint32_t)lb[1] << 16),
                                       (uint32_t)lb[2] | ((uint32_t)lb[3] << 16));
    }
}

// ============================ bf16x3 mma.sync GEMM ============================
// C[BM,BN] tile of A @ B^T.  A:[M,K] hi/lo bf16 row-major, B:[N,K] hi/lo bf16 row-major.
// 512 threads: 16 warps = 4 m-slices (64) x 4 n-slices (32).
// Inner schedule per kk: ldsm{ah,bh,bl} -> 32 mma (ah*bh, ah*bl) -> ldsm al (reuse ah)
//                        -> 16 mma (al*bh). Keeps frag regs at 96.
// MODE 0: GEMM1 — gate tiles (bn<DD): outF = sigmoid(acc) (u);
//                 value tiles: (ohi,olo) = bf16 hi/lo split of acc (vx).
// MODE 1: GEMM2 — outF = acc (cand).
template <int MODE>
__global__ __launch_bounds__(NTHREADS, 1)
void gemm_mma(const __nv_bfloat16* __restrict__ Ahi, const __nv_bfloat16* __restrict__ Alo,
              const __nv_bfloat16* __restrict__ Bhi, const __nv_bfloat16* __restrict__ Blo,
              float* __restrict__ outF,
              __nv_bfloat16* __restrict__ ohi, __nv_bfloat16* __restrict__ olo,
              int ntn)
{
    extern __shared__ char smem[];
    const uint32_t sb = smem_u32(smem);
    const int tid = threadIdx.x;
    const int wid = tid >> 5, lane = tid & 31;

    // CTA swizzle: GROUP_M m-tiles per n-sweep for L2 reuse
    int per_group = GROUP_M * ntn;
    int group = blockIdx.x / per_group;
    int rem = blockIdx.x % per_group;
    const int bm = (group * GROUP_M + (rem % GROUP_M)) * BM;
    const int bn = (rem / GROUP_M) * BN;

    const int wm = wid & 3;   // 4 m-slices of 64
    const int wn = wid >> 2;  // 4 n-slices of 32

    // per-thread ldmatrix smem offsets (stage-invariant)
    uint32_t offA[4], offB[2];
#pragma unroll
    for (int mf = 0; mf < 4; mf++)
        offA[mf] = (uint32_t)(wm * 64 + mf * 16 + (lane & 15)) * ROWB + (lane >> 4) * 16;
#pragma unroll
    for (int p = 0; p < 2; p++)
        offB[p] = (uint32_t)(wn * 32 + p * 16 + ((lane >> 4) & 1) * 8 + (lane & 7)) * ROWB
                  + ((lane >> 3) & 1) * 16;

    float acc[4][4][4];
#pragma unroll
    for (int a = 0; a < 4; a++)
#pragma unroll
        for (int b = 0; b < 4; b++)
#pragma unroll
            for (int e = 0; e < 4; e++) acc[a][b][e] = 0.f;

    const int NST = (NSTAGE * STAGE_B > 232448) ? 3 : NSTAGE;

    auto load_stage = [&](int kc) {
        uint32_t base = sb + (uint32_t)(kc % NST) * STAGE_B;
        int k0 = kc * BK;
        // A: BM*BK*2B = 16384B = 1024 16B-chunks per matrix (2 per thread)
#pragma unroll
        for (int j = 0; j < 2; j++) {
            int ch = tid + j * NTHREADS;
            int row = ch >> 2, kc4 = ch & 3;
            uint32_t doff = (uint32_t)row * ROWB + kc4 * 16;
            size_t ga = (size_t)(bm + row) * DD + k0 + kc4 * 8;
            cp16(base + A_HI_OFF + doff, Ahi + ga);
            cp16(base + A_LO_OFF + doff, Alo + ga);
        }
        // B: BN*BK*2B = 8192B = 512 chunks per matrix (1 per thread)
        {
            int row = tid >> 2, kc4 = tid & 3;
            uint32_t doff = (uint32_t)row * ROWB + kc4 * 16;
            size_t gb = (size_t)(bn + row) * DD + k0 + kc4 * 8;
            cp16(base + B_HI_OFF + doff, Bhi + gb);
            cp16(base + B_LO_OFF + doff, Blo + gb);
        }
        cp_commit();
    };

    load_stage(0);
    load_stage(1);

    const int NKC = DD / BK;   // 32
    for (int kc = 0; kc < NKC; kc++) {
        // wait for stage kc (2 newer groups may still be in flight)
        if (kc + 2 < NKC)      cp_wait<1>();
        else if (kc + 1 < NKC) cp_wait<1>();
        else                   cp_wait<0>();
        __syncthreads();                     // stage kc visible; prev compute done

        uint32_t base = sb + (uint32_t)(kc % NST) * STAGE_B;
#pragma unroll
        for (int kk = 0; kk < 2; kk++) {
            uint32_t ah[4][4], bh[2][4], bl[2][4];
            // front-load all operands for pass 1
#pragma unroll
            for (int mf = 0; mf < 4; mf++)
                ldsm4(ah[mf], base + A_HI_OFF + offA[mf] + kk * 32);
#pragma unroll
            for (int p = 0; p < 2; p++) {
                ldsm4(bh[p], base + B_HI_OFF + offB[p] + kk * 32);
                ldsm4(bl[p], base + B_LO_OFF + offB[p] + kk * 32);
            }
            // pass 1: hi*hi and hi*lo (32 mma, no mid-stream loads)
#pragma unroll
            for (int mf = 0; mf < 4; mf++) {
#pragma unroll
                for (int nf = 0; nf < 4; nf++) {
                    const uint32_t* bh2 = &bh[nf >> 1][(nf & 1) * 2];
                    const uint32_t* bl2 = &bl[nf >> 1][(nf & 1) * 2];
                    mma16816(acc[mf][nf], ah[mf], bh2);
                    mma16816(acc[mf][nf], ah[mf], bl2);
                }
            }
            // reload A_lo over the A_hi fragments (WAR only)
#pragma unroll
            for (int mf = 0; mf < 4; mf++)
                ldsm4(ah[mf], base + A_LO_OFF + offA[mf] + kk * 32);
            // spread the next-stage cp.async burst into the middle of the chunk
            if (kk == 0 && kc + 2 < NKC) load_stage(kc + 2);
            // pass 2: lo*hi (16 mma)
#pragma unroll
            for (int mf = 0; mf < 4; mf++) {
#pragma unroll
                for (int nf = 0; nf < 4; nf++) {
                    const uint32_t* bh2 = &bh[nf >> 1][(nf & 1) * 2];
                    mma16816(acc[mf][nf], ah[mf], bh2);
                }
            }
        }
    }

    // ---- epilogue ----
    const int r0 = bm + wm * 64 + (lane >> 2);
    const int c0 = bn + wn * 32 + (lane & 3) * 2;
    const bool gate = (MODE == 0) && (bn < DD);

#pragma unroll
    for (int mf = 0; mf < 4; mf++) {
        int r = r0 + mf * 16;
#pragma unroll
        for (int nf = 0; nf < 4; nf++) {
            int c = c0 + nf * 8;
            float* a = acc[mf][nf];
            if (MODE == 1) {
                *(float2*)(outF + (size_t)r * DD + c)       = make_float2(a[0], a[1]);
                *(float2*)(outF + (size_t)(r + 8) * DD + c) = make_float2(a[2], a[3]);
            } else if (gate) {
                float2 s0, s1;
                s0.x = 1.f / (1.f + __expf(-a[0]));
                s0.y = 1.f / (1.f + __expf(-a[1]));
                s1.x = 1.f / (1.f + __expf(-a[2]));
                s1.y = 1.f / (1.f + __expf(-a[3]));
                *(float2*)(outF + (size_t)r * DD + c)       = s0;
                *(float2*)(outF + (size_t)(r + 8) * DD + c) = s1;
            } else {
                int cc = c - DD;
                unsigned short hb2[4], lb2[4];
#pragma unroll
                for (int e = 0; e < 4; e++) {
                    __nv_bfloat16 h = __float2bfloat16(a[e]);
                    float rr = a[e] - __bfloat162float(h);
                    hb2[e] = __bfloat16_as_ushort(h);
                    lb2[e] = __bfloat16_as_ushort(__float2bfloat16(rr));
                }
                *(uint32_t*)(ohi + (size_t)r * DD + cc)       = (uint32_t)hb2[0] | ((uint32_t)hb2[1] << 16);
                *(uint32_t*)(ohi + (size_t)(r + 8) * DD + cc) = (uint32_t)hb2[2] | ((uint32_t)hb2[3] << 16);
                *(uint32_t*)(olo + (size_t)r * DD + cc)       = (uint32_t)lb2[0] | ((uint32_t)lb2[1] << 16);
                *(uint32_t*)(olo + (size_t)(r + 8) * DD + cc) = (uint32_t)lb2[2] | ((uint32_t)lb2[3] << 16);
            }
        }
    }
}

// ============================ scan (diagonal recurrence) ============================
// h_t = u*h + (1-u)*c = fma(u, h-c, c). Reads g_u, g_c; writes y in-place into g_c.
__global__ __launch_bounds__(256) void scan_kernel()
{
    int idx = blockIdx.x * blockDim.x + threadIdx.x;   // 0 .. B*D-1
    int b = idx >> 10;
    int d = idx & (DD - 1);
    float* up = g_u + (size_t)b * TT * DD + d;
    float* cp = g_c + (size_t)b * TT * DD + d;
    float h = 0.f;
    for (int t = 0; t < TT; t += 8) {
        float uu[8], cc[8];
#pragma unroll
        for (int j = 0; j < 8; j++) {
            uu[j] = up[(size_t)(t + j) * DD];
            cc[j] = cp[(size_t)(t + j) * DD];
        }
#pragma unroll
        for (int j = 0; j < 8; j++) {
            h = fmaf(uu[j], h - cc[j], cc[j]);
            cc[j] = h;
        }
#pragma unroll
        for (int j = 0; j < 8; j++) cp[(size_t)(t + j) * DD] = cc[j];
    }
}

// ============================ LayerNorm ============================
__global__ __launch_bounds__(256) void ln_kernel(const float* __restrict__ gamma,
                                                 const float* __restrict__ beta,
                                                 float* __restrict__ out)
{
    int row = blockIdx.x;
    int t = threadIdx.x;
    const float4* yr = (const float4*)(g_c + (size_t)row * DD);
    float4 v = yr[t];
    float s = v.x + v.y + v.z + v.w;
    float q = v.x * v.x + v.y * v.y + v.z * v.z + v.w * v.w;

#pragma unroll
    for (int o = 16; o; o >>= 1) {
        s += __shfl_xor_sync(0xFFFFFFFFu, s, o);
        q += __shfl_xor_sync(0xFFFFFFFFu, q, o);
    }
    __shared__ float sw[8], qw[8];
    __shared__ float mu_s, inv_s;
    int w = t >> 5, l = t & 31;
    if (l == 0) { sw[w] = s; qw[w] = q; }
    __syncthreads();
    if (t == 0) {
        float S = 0.f, Q = 0.f;
#pragma unroll
        for (int i = 0; i < 8; i++) { S += sw[i]; Q += qw[i]; }
        float mu = S * (1.f / DD);
        float var = Q * (1.f / DD) - mu * mu;
        mu_s = mu;
        inv_s = rsqrtf(var + LN_EPS);
    }
    __syncthreads();
    float mu = mu_s, inv = inv_s;

    const float4* g4 = (const float4*)gamma;
    const float4* b4 = (const float4*)beta;
    float4 gv = g4[t], bv = b4[t];
    float4 o;
    o.x = (v.x - mu) * inv * gv.x + bv.x;
    o.y = (v.y - mu) * inv * gv.y + bv.y;
    o.z = (v.z - mu) * inv * gv.z + bv.z;
    o.w = (v.w - mu) * inv * gv.w + bv.w;
    ((float4*)(out + (size_t)row * DD))[t] = o;
}

// ============================ host ============================
extern "C" void kernel_launch(void* const* d_in, const int* in_sizes, int n_in,
                              void* d_out, int out_size)
{
    const float* x       = (const float*)d_in[0];
    const float* W_in    = (const float*)d_in[1];
    const float* W_state = (const float*)d_in[2];
    const float* gamma   = (const float*)d_in[3];
    const float* beta    = (const float*)d_in[4];
    float* out = (float*)d_out;

    void *pxh, *pxl, *pwh, *pwl, *psh, *psl, *pvh, *pvl, *pu, *pc;
    cudaGetSymbolAddress(&pxh, g_xhi); cudaGetSymbolAddress(&pxl, g_xlo);
    cudaGetSymbolAddress(&pwh, g_whi); cudaGetSymbolAddress(&pwl, g_wlo);
    cudaGetSymbolAddress(&psh, g_shi); cudaGetSymbolAddress(&psl, g_slo);
    cudaGetSymbolAddress(&pvh, g_vhi); cudaGetSymbolAddress(&pvl, g_vlo);
    cudaGetSymbolAddress(&pu,  g_u);   cudaGetSymbolAddress(&pc,  g_c);

    cudaFuncSetAttribute(gemm_mma<0>, cudaFuncAttributeMaxDynamicSharedMemorySize, SMEM_TOTAL);
    cudaFuncSetAttribute(gemm_mma<1>, cudaFuncAttributeMaxDynamicSharedMemorySize, SMEM_TOTAL);

    // fp32 -> bf16 hi/lo splits
    { int n = MROWS * DD;  split_kernel<<<(n / 4 + 255) / 256, 256>>>(x, (__nv_bfloat16*)pxh, (__nv_bfloat16*)pxl, n); }
    { int n = 2 * DD * DD; split_kernel<<<(n / 4 + 255) / 256, 256>>>(W_in, (__nv_bfloat16*)pwh, (__nv_bfloat16*)pwl, n); }
    { int n = DD * DD;     split_kernel<<<(n / 4 + 255) / 256, 256>>>(W_state, (__nv_bfloat16*)psh, (__nv_bfloat16*)psl, n); }

    // GEMM1: [32768,1024] @ [2048,1024]^T -> u (sigmoid fp32) + vx (bf16 hi/lo)
    {
        int ntm = MROWS / BM, ntn = 2 * DD / BN;   // 128, 16
        gemm_mma<0><<<ntm * ntn, NTHREADS, SMEM_TOTAL>>>(
            (const __nv_bfloat16*)pxh, (const __nv_bfloat16*)pxl,
            (const __nv_bfloat16*)pwh, (const __nv_bfloat16*)pwl,
            (float*)pu, (__nv_bfloat16*)pvh, (__nv_bfloat16*)pvl, ntn);
    }
    // GEMM2: [32768,1024] @ [1024,1024]^T -> cand (fp32)
    {
        int ntm = MROWS / BM, ntn = DD / BN;       // 128, 8
        gemm_mma<1><<<ntm * ntn, NTHREADS, SMEM_TOTAL>>>(
            (const __nv_bfloat16*)pvh, (const __nv_bfloat16*)pvl,
            (const __nv_bfloat16*)psh, (const __nv_bfloat16*)psl,
            (float*)pc, nullptr, nullptr, ntn);
    }

    // scan over T (y written in-place into g_c), then LN
    scan_kernel<<<(BB * DD) / 256, 256>>>();
    ln_kernel<<<MROWS, 256>>>(gamma, beta, out);
}

// round 6
// speedup vs baseline: 3.2417x; 1.0222x over previous
#include <cuda_runtime.h>
#include <cuda_bf16.h>
#include <math.h>
#include <stdint.h>

#define BB 16
#define TT 2048
#define DD 1024
#define MROWS (BB * TT)       // 32768
#define LN_EPS 1e-5f

// ---- GEMM tiling ----
#define BM 256
#define BN 128
#define BK 64                  // bf16 elems per k-chunk (4 kk-steps of 16)
#define NSTAGE 2
#define NTHREADS 512
#define ROWB 144               // 128B data + 16B pad (conflict-free ldmatrix: stride 9 mod 8)
#define A_HI_OFF 0
#define A_LO_OFF (BM * ROWB)                     // 36864
#define B_HI_OFF (2 * BM * ROWB)                 // 73728
#define B_LO_OFF (2 * BM * ROWB + BN * ROWB)     // 92160
#define STAGE_B  (2 * BM * ROWB + 2 * BN * ROWB) // 110592
#define SMEM_TOTAL (NSTAGE * STAGE_B)            // 221184 <= 227KB
#define GROUP_M 8

// ---- scratch (__device__ globals; no cudaMalloc allowed) ----
__device__ __nv_bfloat16 g_xhi[(size_t)MROWS * DD];
__device__ __nv_bfloat16 g_xlo[(size_t)MROWS * DD];
__device__ __nv_bfloat16 g_whi[(size_t)2 * DD * DD];
__device__ __nv_bfloat16 g_wlo[(size_t)2 * DD * DD];
__device__ __nv_bfloat16 g_shi[(size_t)DD * DD];
__device__ __nv_bfloat16 g_slo[(size_t)DD * DD];
__device__ __nv_bfloat16 g_vhi[(size_t)MROWS * DD];
__device__ __nv_bfloat16 g_vlo[(size_t)MROWS * DD];
__device__ float g_u[(size_t)MROWS * DD];
__device__ float g_c[(size_t)MROWS * DD];

// ============================ device helpers ============================
__device__ __forceinline__ uint32_t smem_u32(const void* p) {
    uint32_t a;
    asm("{ .reg .u64 t; cvta.to.shared.u64 t, %1; cvt.u32.u64 %0, t; }" : "=r"(a) : "l"(p));
    return a;
}
__device__ __forceinline__ void cp16(uint32_t dst, const void* src) {
    asm volatile("cp.async.cg.shared.global [%0], [%1], 16;" :: "r"(dst), "l"(src));
}
__device__ __forceinline__ void cp_commit() {
    asm volatile("cp.async.commit_group;" ::: "memory");
}
template <int N>
__device__ __forceinline__ void cp_wait() {
    asm volatile("cp.async.wait_group %0;" :: "n"(N) : "memory");
}
__device__ __forceinline__ void ldsm4(uint32_t* r, uint32_t a) {
    asm volatile("ldmatrix.sync.aligned.m8n8.x4.shared.b16 {%0,%1,%2,%3}, [%4];"
                 : "=r"(r[0]), "=r"(r[1]), "=r"(r[2]), "=r"(r[3]) : "r"(a));
}
__device__ __forceinline__ void mma16816(float* c, const uint32_t* a, const uint32_t* b) {
    asm volatile(
        "mma.sync.aligned.m16n8k16.row.col.f32.bf16.bf16.f32 "
        "{%0,%1,%2,%3},{%4,%5,%6,%7},{%8,%9},{%0,%1,%2,%3};"
        : "+f"(c[0]), "+f"(c[1]), "+f"(c[2]), "+f"(c[3])
        : "r"(a[0]), "r"(a[1]), "r"(a[2]), "r"(a[3]), "r"(b[0]), "r"(b[1]));
}

// ============================ split fp32 -> bf16 hi/lo ============================
__global__ __launch_bounds__(256) void split_kernel(
    const float* __restrict__ src, __nv_bfloat16* __restrict__ hi,
    __nv_bfloat16* __restrict__ lo, int n)
{
    int i = (blockIdx.x * blockDim.x + threadIdx.x) * 4;
    if (i < n) {
        float4 v = *(const float4*)(src + i);
        float vv[4] = {v.x, v.y, v.z, v.w};
        unsigned short hb[4], lb[4];
#pragma unroll
        for (int e = 0; e < 4; e++) {
            __nv_bfloat16 h = __float2bfloat16(vv[e]);
            float r = vv[e] - __bfloat162float(h);
            hb[e] = __bfloat16_as_ushort(h);
            lb[e] = __bfloat16_as_ushort(__float2bfloat16(r));
        }
        *(uint2*)(hi + i) = make_uint2((uint32_t)hb[0] | ((uint32_t)hb[1] << 16),
                                       (uint32_t)hb[2] | ((uint32_t)hb[3] << 16));
        *(uint2*)(lo + i) = make_uint2((uint32_t)lb[0] | ((uint32_t)lb[1] << 16),
                                       (uint32_t)lb[2] | ((uint32_t)lb[3] << 16));
    }
}

// ============================ bf16x3 mma.sync GEMM ============================
// C[BM,BN] tile of A @ B^T.  A:[M,K] hi/lo bf16 row-major, B:[N,K] hi/lo bf16 row-major.
// 512 threads: 16 warps = 4 m-slices (64) x 4 n-slices (32).
// BK=64 chunk = 4 kk-steps; 2-stage smem ring; next-stage cp.async issued mid-chunk.
// MODE 0: GEMM1 — gate tiles (bn<DD): outF = sigmoid(acc) (u);
//                 value tiles: (ohi,olo) = bf16 hi/lo split of acc (vx).
// MODE 1: GEMM2 — outF = acc (cand).
template <int MODE>
__global__ __launch_bounds__(NTHREADS, 1)
void gemm_mma(const __nv_bfloat16* __restrict__ Ahi, const __nv_bfloat16* __restrict__ Alo,
              const __nv_bfloat16* __restrict__ Bhi, const __nv_bfloat16* __restrict__ Blo,
              float* __restrict__ outF,
              __nv_bfloat16* __restrict__ ohi, __nv_bfloat16* __restrict__ olo,
              int ntn)
{
    extern __shared__ char smem[];
    const uint32_t sb = smem_u32(smem);
    const int tid = threadIdx.x;
    const int wid = tid >> 5, lane = tid & 31;

    // CTA swizzle: GROUP_M m-tiles per n-sweep for L2 reuse
    int per_group = GROUP_M * ntn;
    int group = blockIdx.x / per_group;
    int rem = blockIdx.x % per_group;
    const int bm = (group * GROUP_M + (rem % GROUP_M)) * BM;
    const int bn = (rem / GROUP_M) * BN;

    const int wm = wid & 3;   // 4 m-slices of 64
    const int wn = wid >> 2;  // 4 n-slices of 32

    // per-thread ldmatrix smem offsets (stage-invariant; kk adds kk*32 bytes)
    uint32_t offA[4], offB[2];
#pragma unroll
    for (int mf = 0; mf < 4; mf++)
        offA[mf] = (uint32_t)(wm * 64 + mf * 16 + (lane & 15)) * ROWB + (lane >> 4) * 16;
#pragma unroll
    for (int p = 0; p < 2; p++)
        offB[p] = (uint32_t)(wn * 32 + p * 16 + ((lane >> 4) & 1) * 8 + (lane & 7)) * ROWB
                  + ((lane >> 3) & 1) * 16;

    float acc[4][4][4];
#pragma unroll
    for (int a = 0; a < 4; a++)
#pragma unroll
        for (int b = 0; b < 4; b++)
#pragma unroll
            for (int e = 0; e < 4; e++) acc[a][b][e] = 0.f;

    // per-stage loads: A = 2048 16B-chunks x2(hi/lo) -> 8 cp/thread,
    //                  B = 1024 x2 -> 4 cp/thread. Split into two halves.
    auto load_half = [&](int kc, int half) {
        uint32_t base = sb + (uint32_t)(kc % NSTAGE) * STAGE_B;
        int k0 = kc * BK;
        // A: j in {0,1} for half 0, {2,3} for half 1
#pragma unroll
        for (int j = 0; j < 2; j++) {
            int ch = tid + (half * 2 + j) * NTHREADS;
            int row = ch >> 3, kc8 = ch & 7;
            uint32_t doff = (uint32_t)row * ROWB + kc8 * 16;
            size_t ga = (size_t)(bm + row) * DD + k0 + kc8 * 8;
            cp16(base + A_HI_OFF + doff, Ahi + ga);
            cp16(base + A_LO_OFF + doff, Alo + ga);
        }
        // B: one j per half
        {
            int ch = tid + half * NTHREADS;
            int row = ch >> 3, kc8 = ch & 7;
            uint32_t doff = (uint32_t)row * ROWB + kc8 * 16;
            size_t gb = (size_t)(bn + row) * DD + k0 + kc8 * 8;
            cp16(base + B_HI_OFF + doff, Bhi + gb);
            cp16(base + B_LO_OFF + doff, Blo + gb);
        }
    };

    load_half(0, 0);
    load_half(0, 1);
    cp_commit();

    const int NKC = DD / BK;   // 16
    for (int kc = 0; kc < NKC; kc++) {
        cp_wait<0>();
        __syncthreads();                     // stage kc visible; all warps done with other buffer

        uint32_t base = sb + (uint32_t)(kc % NSTAGE) * STAGE_B;
#pragma unroll
        for (int kk = 0; kk < 4; kk++) {
            uint32_t ah[4][4], bh[2][4], bl[2][4];
            // front-load all operands for pass 1
#pragma unroll
            for (int mf = 0; mf < 4; mf++)
                ldsm4(ah[mf], base + A_HI_OFF + offA[mf] + kk * 32);
#pragma unroll
            for (int p = 0; p < 2; p++) {
                ldsm4(bh[p], base + B_HI_OFF + offB[p] + kk * 32);
                ldsm4(bl[p], base + B_LO_OFF + offB[p] + kk * 32);
            }
            // pass 1: hi*hi and hi*lo (32 mma)
#pragma unroll
            for (int mf = 0; mf < 4; mf++) {
#pragma unroll
                for (int nf = 0; nf < 4; nf++) {
                    const uint32_t* bh2 = &bh[nf >> 1][(nf & 1) * 2];
                    const uint32_t* bl2 = &bl[nf >> 1][(nf & 1) * 2];
                    mma16816(acc[mf][nf], ah[mf], bh2);
                    mma16816(acc[mf][nf], ah[mf], bl2);
                }
            }
            // reload A_lo over the A_hi fragments (WAR only)
#pragma unroll
            for (int mf = 0; mf < 4; mf++)
                ldsm4(ah[mf], base + A_LO_OFF + offA[mf] + kk * 32);
            // spread next-stage cp.async issue into the middle of the chunk
            if (kc + 1 < NKC) {
                if (kk == 0) load_half(kc + 1, 0);
                if (kk == 1) { load_half(kc + 1, 1); cp_commit(); }
            }
            // pass 2: lo*hi (16 mma)
#pragma unroll
            for (int mf = 0; mf < 4; mf++) {
#pragma unroll
                for (int nf = 0; nf < 4; nf++) {
                    const uint32_t* bh2 = &bh[nf >> 1][(nf & 1) * 2];
                    mma16816(acc[mf][nf], ah[mf], bh2);
                }
            }
        }
    }

    // ---- epilogue ----
    const int r0 = bm + wm * 64 + (lane >> 2);
    const int c0 = bn + wn * 32 + (lane & 3) * 2;
    const bool gate = (MODE == 0) && (bn < DD);

#pragma unroll
    for (int mf = 0; mf < 4; mf++) {
        int r = r0 + mf * 16;
#pragma unroll
        for (int nf = 0; nf < 4; nf++) {
            int c = c0 + nf * 8;
            float* a = acc[mf][nf];
            if (MODE == 1) {
                *(float2*)(outF + (size_t)r * DD + c)       = make_float2(a[0], a[1]);
                *(float2*)(outF + (size_t)(r + 8) * DD + c) = make_float2(a[2], a[3]);
            } else if (gate) {
                float2 s0, s1;
                s0.x = 1.f / (1.f + __expf(-a[0]));
                s0.y = 1.f / (1.f + __expf(-a[1]));
                s1.x = 1.f / (1.f + __expf(-a[2]));
                s1.y = 1.f / (1.f + __expf(-a[3]));
                *(float2*)(outF + (size_t)r * DD + c)       = s0;
                *(float2*)(outF + (size_t)(r + 8) * DD + c) = s1;
            } else {
                int cc = c - DD;
                unsigned short hb2[4], lb2[4];
#pragma unroll
                for (int e = 0; e < 4; e++) {
                    __nv_bfloat16 h = __float2bfloat16(a[e]);
                    float rr = a[e] - __bfloat162float(h);
                    hb2[e] = __bfloat16_as_ushort(h);
                    lb2[e] = __bfloat16_as_ushort(__float2bfloat16(rr));
                }
                *(uint32_t*)(ohi + (size_t)r * DD + cc)       = (uint32_t)hb2[0] | ((uint32_t)hb2[1] << 16);
                *(uint32_t*)(ohi + (size_t)(r + 8) * DD + cc) = (uint32_t)hb2[2] | ((uint32_t)hb2[3] << 16);
                *(uint32_t*)(olo + (size_t)r * DD + cc)       = (uint32_t)lb2[0] | ((uint32_t)lb2[1] << 16);
                *(uint32_t*)(olo + (size_t)(r + 8) * DD + cc) = (uint32_t)lb2[2] | ((uint32_t)lb2[3] << 16);
            }
        }
    }
}

// ============================ scan (diagonal recurrence) ============================
// h_t = u*h + (1-u)*c = fma(u, h-c, c). Reads g_u, g_c; writes y in-place into g_c.
__global__ __launch_bounds__(256) void scan_kernel()
{
    int idx = blockIdx.x * blockDim.x + threadIdx.x;   // 0 .. B*D-1
    int b = idx >> 10;
    int d = idx & (DD - 1);
    float* up = g_u + (size_t)b * TT * DD + d;
    float* cp = g_c + (size_t)b * TT * DD + d;
    float h = 0.f;
    for (int t = 0; t < TT; t += 8) {
        float uu[8], cc[8];
#pragma unroll
        for (int j = 0; j < 8; j++) {
            uu[j] = up[(size_t)(t + j) * DD];
            cc[j] = cp[(size_t)(t + j) * DD];
        }
#pragma unroll
        for (int j = 0; j < 8; j++) {
            h = fmaf(uu[j], h - cc[j], cc[j]);
            cc[j] = h;
        }
#pragma unroll
        for (int j = 0; j < 8; j++) cp[(size_t)(t + j) * DD] = cc[j];
    }
}

// ============================ LayerNorm ============================
__global__ __launch_bounds__(256) void ln_kernel(const float* __restrict__ gamma,
                                                 const float* __restrict__ beta,
                                                 float* __restrict__ out)
{
    int row = blockIdx.x;
    int t = threadIdx.x;
    const float4* yr = (const float4*)(g_c + (size_t)row * DD);
    float4 v = yr[t];
    float s = v.x + v.y + v.z + v.w;
    float q = v.x * v.x + v.y * v.y + v.z * v.z + v.w * v.w;

#pragma unroll
    for (int o = 16; o; o >>= 1) {
        s += __shfl_xor_sync(0xFFFFFFFFu, s, o);
        q += __shfl_xor_sync(0xFFFFFFFFu, q, o);
    }
    __shared__ float sw[8], qw[8];
    __shared__ float mu_s, inv_s;
    int w = t >> 5, l = t & 31;
    if (l == 0) { sw[w] = s; qw[w] = q; }
    __syncthreads();
    if (t == 0) {
        float S = 0.f, Q = 0.f;
#pragma unroll
        for (int i = 0; i < 8; i++) { S += sw[i]; Q += qw[i]; }
        float mu = S * (1.f / DD);
        float var = Q * (1.f / DD) - mu * mu;
        mu_s = mu;
        inv_s = rsqrtf(var + LN_EPS);
    }
    __syncthreads();
    float mu = mu_s, inv = inv_s;

    const float4* g4 = (const float4*)gamma;
    const float4* b4 = (const float4*)beta;
    float4 gv = g4[t], bv = b4[t];
    float4 o;
    o.x = (v.x - mu) * inv * gv.x + bv.x;
    o.y = (v.y - mu) * inv * gv.y + bv.y;
    o.z = (v.z - mu) * inv * gv.z + bv.z;
    o.w = (v.w - mu) * inv * gv.w + bv.w;
    ((float4*)(out + (size_t)row * DD))[t] = o;
}

// ============================ host ============================
extern "C" void kernel_launch(void* const* d_in, const int* in_sizes, int n_in,
                              void* d_out, int out_size)
{
    const float* x       = (const float*)d_in[0];
    const float* W_in    = (const float*)d_in[1];
    const float* W_state = (const float*)d_in[2];
    const float* gamma   = (const float*)d_in[3];
    const float* beta    = (const float*)d_in[4];
    float* out = (float*)d_out;

    void *pxh, *pxl, *pwh, *pwl, *psh, *psl, *pvh, *pvl, *pu, *pc;
    cudaGetSymbolAddress(&pxh, g_xhi); cudaGetSymbolAddress(&pxl, g_xlo);
    cudaGetSymbolAddress(&pwh, g_whi); cudaGetSymbolAddress(&pwl, g_wlo);
    cudaGetSymbolAddress(&psh, g_shi); cudaGetSymbolAddress(&psl, g_slo);
    cudaGetSymbolAddress(&pvh, g_vhi); cudaGetSymbolAddress(&pvl, g_vlo);
    cudaGetSymbolAddress(&pu,  g_u);   cudaGetSymbolAddress(&pc,  g_c);

    cudaFuncSetAttribute(gemm_mma<0>, cudaFuncAttributeMaxDynamicSharedMemorySize, SMEM_TOTAL);
    cudaFuncSetAttribute(gemm_mma<1>, cudaFuncAttributeMaxDynamicSharedMemorySize, SMEM_TOTAL);

    // fp32 -> bf16 hi/lo splits
    { int n = MROWS * DD;  split_kernel<<<(n / 4 + 255) / 256, 256>>>(x, (__nv_bfloat16*)pxh, (__nv_bfloat16*)pxl, n); }
    { int n = 2 * DD * DD; split_kernel<<<(n / 4 + 255) / 256, 256>>>(W_in, (__nv_bfloat16*)pwh, (__nv_bfloat16*)pwl, n); }
    { int n = DD * DD;     split_kernel<<<(n / 4 + 255) / 256, 256>>>(W_state, (__nv_bfloat16*)psh, (__nv_bfloat16*)psl, n); }

    // GEMM1: [32768,1024] @ [2048,1024]^T -> u (sigmoid fp32) + vx (bf16 hi/lo)
    {
        int ntm = MROWS / BM, ntn = 2 * DD / BN;   // 128, 16
        gemm_mma<0><<<ntm * ntn, NTHREADS, SMEM_TOTAL>>>(
            (const __nv_bfloat16*)pxh, (const __nv_bfloat16*)pxl,
            (const __nv_bfloat16*)pwh, (const __nv_bfloat16*)pwl,
            (float*)pu, (__nv_bfloat16*)pvh, (__nv_bfloat16*)pvl, ntn);
    }
    // GEMM2: [32768,1024] @ [1024,1024]^T -> cand (fp32)
    {
        int ntm = MROWS / BM, ntn = DD / BN;       // 128, 8
        gemm_mma<1><<<ntm * ntn, NTHREADS, SMEM_TOTAL>>>(
            (const __nv_bfloat16*)pvh, (const __nv_bfloat16*)pvl,
            (const __nv_bfloat16*)psh, (const __nv_bfloat16*)psl,
            (float*)pc, nullptr, nullptr, ntn);
    }

    // scan over T (y written in-place into g_c), then LN
    scan_kernel<<<(BB * DD) / 256, 256>>>();
    ln_kernel<<<MROWS, 256>>>(gamma, beta, out);
}

// round 7
// speedup vs baseline: 3.7829x; 1.1669x over previous
#include <cuda_runtime.h>
#include <cuda_fp16.h>
#include <math.h>
#include <stdint.h>

#define BB 16
#define TT 2048
#define DD 1024
#define MROWS (BB * TT)       // 32768
#define LN_EPS 1e-5f

// ---- GEMM tiling ----
#define BM 256
#define BN 128
#define BK 64                  // fp16 elems per k-chunk (4 kk-steps of 16)
#define NSTAGE 2
#define NTHREADS 512
#define ROWB 144               // 128B data + 16B pad (conflict-free ldmatrix)
#define A_HI_OFF 0
#define A_LO_OFF (BM * ROWB)                     // 36864
#define B_HI_OFF (2 * BM * ROWB)                 // 73728
#define STAGE_B  (2 * BM * ROWB + BN * ROWB)     // 92160
#define SMEM_TOTAL (NSTAGE * STAGE_B)            // 184320 <= 227KB
#define GROUP_M 8

// ---- scratch (__device__ globals; no cudaMalloc allowed) ----
__device__ __half g_xhi[(size_t)MROWS * DD];
__device__ __half g_xlo[(size_t)MROWS * DD];
__device__ __half g_wh [(size_t)2 * DD * DD];    // W_in fp16
__device__ __half g_sh [(size_t)DD * DD];        // W_state fp16
__device__ __half g_vhi[(size_t)MROWS * DD];
__device__ __half g_vlo[(size_t)MROWS * DD];
__device__ float g_u[(size_t)MROWS * DD];
__device__ float g_c[(size_t)MROWS * DD];

// ============================ device helpers ============================
__device__ __forceinline__ uint32_t smem_u32(const void* p) {
    uint32_t a;
    asm("{ .reg .u64 t; cvta.to.shared.u64 t, %1; cvt.u32.u64 %0, t; }" : "=r"(a) : "l"(p));
    return a;
}
__device__ __forceinline__ void cp16(uint32_t dst, const void* src) {
    asm volatile("cp.async.cg.shared.global [%0], [%1], 16;" :: "r"(dst), "l"(src));
}
__device__ __forceinline__ void cp_commit() {
    asm volatile("cp.async.commit_group;" ::: "memory");
}
template <int N>
__device__ __forceinline__ void cp_wait() {
    asm volatile("cp.async.wait_group %0;" :: "n"(N) : "memory");
}
__device__ __forceinline__ void ldsm4(uint32_t* r, uint32_t a) {
    asm volatile("ldmatrix.sync.aligned.m8n8.x4.shared.b16 {%0,%1,%2,%3}, [%4];"
                 : "=r"(r[0]), "=r"(r[1]), "=r"(r[2]), "=r"(r[3]) : "r"(a));
}
__device__ __forceinline__ void mma16816(float* c, const uint32_t* a, const uint32_t* b) {
    asm volatile(
        "mma.sync.aligned.m16n8k16.row.col.f32.f16.f16.f32 "
        "{%0,%1,%2,%3},{%4,%5,%6,%7},{%8,%9},{%0,%1,%2,%3};"
        : "+f"(c[0]), "+f"(c[1]), "+f"(c[2]), "+f"(c[3])
        : "r"(a[0]), "r"(a[1]), "r"(a[2]), "r"(a[3]), "r"(b[0]), "r"(b[1]));
}

// ============================ conversions ============================
// fp32 -> fp16 hi + lo residual
__global__ __launch_bounds__(256) void split_kernel(
    const float* __restrict__ src, __half* __restrict__ hi,
    __half* __restrict__ lo, int n)
{
    int i = (blockIdx.x * blockDim.x + threadIdx.x) * 4;
    if (i < n) {
        float4 v = *(const float4*)(src + i);
        float vv[4] = {v.x, v.y, v.z, v.w};
        unsigned short hb[4], lb[4];
#pragma unroll
        for (int e = 0; e < 4; e++) {
            __half h = __float2half_rn(vv[e]);
            float r = vv[e] - __half2float(h);
            hb[e] = __half_as_ushort(h);
            lb[e] = __half_as_ushort(__float2half_rn(r));
        }
        *(uint2*)(hi + i) = make_uint2((uint32_t)hb[0] | ((uint32_t)hb[1] << 16),
                                       (uint32_t)hb[2] | ((uint32_t)hb[3] << 16));
        *(uint2*)(lo + i) = make_uint2((uint32_t)lb[0] | ((uint32_t)lb[1] << 16),
                                       (uint32_t)lb[2] | ((uint32_t)lb[3] << 16));
    }
}

// fp32 -> fp16 (single)
__global__ __launch_bounds__(256) void conv_kernel(
    const float* __restrict__ src, __half* __restrict__ dst, int n)
{
    int i = (blockIdx.x * blockDim.x + threadIdx.x) * 4;
    if (i < n) {
        float4 v = *(const float4*)(src + i);
        unsigned short hb[4];
        hb[0] = __half_as_ushort(__float2half_rn(v.x));
        hb[1] = __half_as_ushort(__float2half_rn(v.y));
        hb[2] = __half_as_ushort(__float2half_rn(v.z));
        hb[3] = __half_as_ushort(__float2half_rn(v.w));
        *(uint2*)(dst + i) = make_uint2((uint32_t)hb[0] | ((uint32_t)hb[1] << 16),
                                        (uint32_t)hb[2] | ((uint32_t)hb[3] << 16));
    }
}

// ============================ fp16x2 mma.sync GEMM ============================
// C[BM,BN] tile of A @ B^T.  A:[M,K] fp16 hi/lo row-major, B:[N,K] fp16 row-major.
// acc = Ahi@B^T + Alo@B^T  (B residual dropped: ~2e-4 rel, under 1e-3 gate)
// 512 threads: 16 warps = 4 m-slices (64) x 4 n-slices (32).
// MODE 0: GEMM1 — gate tiles (bn<DD): outF = sigmoid(acc) (u);
//                 value tiles: (ohi,olo) = fp16 hi/lo split of acc (vx).
// MODE 1: GEMM2 — outF = acc (cand).
template <int MODE>
__global__ __launch_bounds__(NTHREADS, 1)
void gemm_mma(const __half* __restrict__ Ahi, const __half* __restrict__ Alo,
              const __half* __restrict__ Bh,
              float* __restrict__ outF,
              __half* __restrict__ ohi, __half* __restrict__ olo,
              int ntn)
{
    extern __shared__ char smem[];
    const uint32_t sb = smem_u32(smem);
    const int tid = threadIdx.x;
    const int wid = tid >> 5, lane = tid & 31;

    // CTA swizzle: GROUP_M m-tiles per n-sweep for L2 reuse
    int per_group = GROUP_M * ntn;
    int group = blockIdx.x / per_group;
    int rem = blockIdx.x % per_group;
    const int bm = (group * GROUP_M + (rem % GROUP_M)) * BM;
    const int bn = (rem / GROUP_M) * BN;

    const int wm = wid & 3;   // 4 m-slices of 64
    const int wn = wid >> 2;  // 4 n-slices of 32

    // per-thread ldmatrix smem offsets (stage-invariant; kk adds kk*32 bytes)
    uint32_t offA[4], offB[2];
#pragma unroll
    for (int mf = 0; mf < 4; mf++)
        offA[mf] = (uint32_t)(wm * 64 + mf * 16 + (lane & 15)) * ROWB + (lane >> 4) * 16;
#pragma unroll
    for (int p = 0; p < 2; p++)
        offB[p] = (uint32_t)(wn * 32 + p * 16 + ((lane >> 4) & 1) * 8 + (lane & 7)) * ROWB
                  + ((lane >> 3) & 1) * 16;

    float acc[4][4][4];
#pragma unroll
    for (int a = 0; a < 4; a++)
#pragma unroll
        for (int b = 0; b < 4; b++)
#pragma unroll
            for (int e = 0; e < 4; e++) acc[a][b][e] = 0.f;

    // per-stage loads: A hi+lo = 8 cp/thread, B = 2 cp/thread; split in halves.
    auto load_half = [&](int kc, int half) {
        uint32_t base = sb + (uint32_t)(kc % NSTAGE) * STAGE_B;
        int k0 = kc * BK;
#pragma unroll
        for (int j = 0; j < 2; j++) {
            int ch = tid + (half * 2 + j) * NTHREADS;   // [0, 2048)
            int row = ch >> 3, kc8 = ch & 7;
            uint32_t doff = (uint32_t)row * ROWB + kc8 * 16;
            size_t ga = (size_t)(bm + row) * DD + k0 + kc8 * 8;
            cp16(base + A_HI_OFF + doff, Ahi + ga);
            cp16(base + A_LO_OFF + doff, Alo + ga);
        }
        {
            int ch = tid + half * NTHREADS;             // [0, 1024)
            int row = ch >> 3, kc8 = ch & 7;
            uint32_t doff = (uint32_t)row * ROWB + kc8 * 16;
            size_t gb = (size_t)(bn + row) * DD + k0 + kc8 * 8;
            cp16(base + B_HI_OFF + doff, Bh + gb);
        }
    };

    load_half(0, 0);
    load_half(0, 1);
    cp_commit();

    const int NKC = DD / BK;   // 16
    for (int kc = 0; kc < NKC; kc++) {
        cp_wait<0>();
        __syncthreads();                     // stage kc visible; all warps done with other buffer

        uint32_t base = sb + (uint32_t)(kc % NSTAGE) * STAGE_B;
#pragma unroll
        for (int kk = 0; kk < 4; kk++) {
            uint32_t ah[4][4], al[4][4], bh[2][4];
            // front-load all operands (10 ldsm)
#pragma unroll
            for (int mf = 0; mf < 4; mf++) {
                ldsm4(ah[mf], base + A_HI_OFF + offA[mf] + kk * 32);
                ldsm4(al[mf], base + A_LO_OFF + offA[mf] + kk * 32);
            }
#pragma unroll
            for (int p = 0; p < 2; p++)
                ldsm4(bh[p], base + B_HI_OFF + offB[p] + kk * 32);
            // spread next-stage cp.async issue into the middle of the chunk
            if (kc + 1 < NKC) {
                if (kk == 0) load_half(kc + 1, 0);
                if (kk == 1) { load_half(kc + 1, 1); cp_commit(); }
            }
            // 32 mma, uninterrupted
#pragma unroll
            for (int mf = 0; mf < 4; mf++) {
#pragma unroll
                for (int nf = 0; nf < 4; nf++) {
                    const uint32_t* b2 = &bh[nf >> 1][(nf & 1) * 2];
                    mma16816(acc[mf][nf], ah[mf], b2);
                    mma16816(acc[mf][nf], al[mf], b2);
                }
            }
        }
    }

    // ---- epilogue ----
    const int r0 = bm + wm * 64 + (lane >> 2);
    const int c0 = bn + wn * 32 + (lane & 3) * 2;
    const bool gate = (MODE == 0) && (bn < DD);

#pragma unroll
    for (int mf = 0; mf < 4; mf++) {
        int r = r0 + mf * 16;
#pragma unroll
        for (int nf = 0; nf < 4; nf++) {
            int c = c0 + nf * 8;
            float* a = acc[mf][nf];
            if (MODE == 1) {
                *(float2*)(outF + (size_t)r * DD + c)       = make_float2(a[0], a[1]);
                *(float2*)(outF + (size_t)(r + 8) * DD + c) = make_float2(a[2], a[3]);
            } else if (gate) {
                float2 s0, s1;
                s0.x = 1.f / (1.f + __expf(-a[0]));
                s0.y = 1.f / (1.f + __expf(-a[1]));
                s1.x = 1.f / (1.f + __expf(-a[2]));
                s1.y = 1.f / (1.f + __expf(-a[3]));
                *(float2*)(outF + (size_t)r * DD + c)       = s0;
                *(float2*)(outF + (size_t)(r + 8) * DD + c) = s1;
            } else {
                int cc = c - DD;
                unsigned short hb2[4], lb2[4];
#pragma unroll
                for (int e = 0; e < 4; e++) {
                    __half h = __float2half_rn(a[e]);
                    float rr = a[e] - __half2float(h);
                    hb2[e] = __half_as_ushort(h);
                    lb2[e] = __half_as_ushort(__float2half_rn(rr));
                }
                *(uint32_t*)(ohi + (size_t)r * DD + cc)       = (uint32_t)hb2[0] | ((uint32_t)hb2[1] << 16);
                *(uint32_t*)(ohi + (size_t)(r + 8) * DD + cc) = (uint32_t)hb2[2] | ((uint32_t)hb2[3] << 16);
                *(uint32_t*)(olo + (size_t)r * DD + cc)       = (uint32_t)lb2[0] | ((uint32_t)lb2[1] << 16);
                *(uint32_t*)(olo + (size_t)(r + 8) * DD + cc) = (uint32_t)lb2[2] | ((uint32_t)lb2[3] << 16);
            }
        }
    }
}

// ============================ scan (diagonal recurrence) ============================
// h_t = u*h + (1-u)*c = fma(u, h-c, c). Reads g_u, g_c; writes y in-place into g_c.
__global__ __launch_bounds__(256) void scan_kernel()
{
    int idx = blockIdx.x * blockDim.x + threadIdx.x;   // 0 .. B*D-1
    int b = idx >> 10;
    int d = idx & (DD - 1);
    float* up = g_u + (size_t)b * TT * DD + d;
    float* cp = g_c + (size_t)b * TT * DD + d;
    float h = 0.f;
    for (int t = 0; t < TT; t += 8) {
        float uu[8], cc[8];
#pragma unroll
        for (int j = 0; j < 8; j++) {
            uu[j] = up[(size_t)(t + j) * DD];
            cc[j] = cp[(size_t)(t + j) * DD];
        }
#pragma unroll
        for (int j = 0; j < 8; j++) {
            h = fmaf(uu[j], h - cc[j], cc[j]);
            cc[j] = h;
        }
#pragma unroll
        for (int j = 0; j < 8; j++) cp[(size_t)(t + j) * DD] = cc[j];
    }
}

// ============================ LayerNorm ============================
__global__ __launch_bounds__(256) void ln_kernel(const float* __restrict__ gamma,
                                                 const float* __restrict__ beta,
                                                 float* __restrict__ out)
{
    int row = blockIdx.x;
    int t = threadIdx.x;
    const float4* yr = (const float4*)(g_c + (size_t)row * DD);
    float4 v = yr[t];
    float s = v.x + v.y + v.z + v.w;
    float q = v.x * v.x + v.y * v.y + v.z * v.z + v.w * v.w;

#pragma unroll
    for (int o = 16; o; o >>= 1) {
        s += __shfl_xor_sync(0xFFFFFFFFu, s, o);
        q += __shfl_xor_sync(0xFFFFFFFFu, q, o);
    }
    __shared__ float sw[8], qw[8];
    __shared__ float mu_s, inv_s;
    int w = t >> 5, l = t & 31;
    if (l == 0) { sw[w] = s; qw[w] = q; }
    __syncthreads();
    if (t == 0) {
        float S = 0.f, Q = 0.f;
#pragma unroll
        for (int i = 0; i < 8; i++) { S += sw[i]; Q += qw[i]; }
        float mu = S * (1.f / DD);
        float var = Q * (1.f / DD) - mu * mu;
        mu_s = mu;
        inv_s = rsqrtf(var + LN_EPS);
    }
    __syncthreads();
    float mu = mu_s, inv = inv_s;

    const float4* g4 = (const float4*)gamma;
    const float4* b4 = (const float4*)beta;
    float4 gv = g4[t], bv = b4[t];
    float4 o;
    o.x = (v.x - mu) * inv * gv.x + bv.x;
    o.y = (v.y - mu) * inv * gv.y + bv.y;
    o.z = (v.z - mu) * inv * gv.z + bv.z;
    o.w = (v.w - mu) * inv * gv.w + bv.w;
    ((float4*)(out + (size_t)row * DD))[t] = o;
}

// ============================ host ============================
extern "C" void kernel_launch(void* const* d_in, const int* in_sizes, int n_in,
                              void* d_out, int out_size)
{
    const float* x       = (const float*)d_in[0];
    const float* W_in    = (const float*)d_in[1];
    const float* W_state = (const float*)d_in[2];
    const float* gamma   = (const float*)d_in[3];
    const float* beta    = (const float*)d_in[4];
    float* out = (float*)d_out;

    void *pxh, *pxl, *pwh, *psh, *pvh, *pvl, *pu, *pc;
    cudaGetSymbolAddress(&pxh, g_xhi); cudaGetSymbolAddress(&pxl, g_xlo);
    cudaGetSymbolAddress(&pwh, g_wh);  cudaGetSymbolAddress(&psh, g_sh);
    cudaGetSymbolAddress(&pvh, g_vhi); cudaGetSymbolAddress(&pvl, g_vlo);
    cudaGetSymbolAddress(&pu,  g_u);   cudaGetSymbolAddress(&pc,  g_c);

    cudaFuncSetAttribute(gemm_mma<0>, cudaFuncAttributeMaxDynamicSharedMemorySize, SMEM_TOTAL);
    cudaFuncSetAttribute(gemm_mma<1>, cudaFuncAttributeMaxDynamicSharedMemorySize, SMEM_TOTAL);

    // conversions
    { int n = MROWS * DD;  split_kernel<<<(n / 4 + 255) / 256, 256>>>(x, (__half*)pxh, (__half*)pxl, n); }
    { int n = 2 * DD * DD; conv_kernel<<<(n / 4 + 255) / 256, 256>>>(W_in, (__half*)pwh, n); }
    { int n = DD * DD;     conv_kernel<<<(n / 4 + 255) / 256, 256>>>(W_state, (__half*)psh, n); }

    // GEMM1: [32768,1024] @ [2048,1024]^T -> u (sigmoid fp32) + vx (fp16 hi/lo)
    {
        int ntm = MROWS / BM, ntn = 2 * DD / BN;   // 128, 16
        gemm_mma<0><<<ntm * ntn, NTHREADS, SMEM_TOTAL>>>(
            (const __half*)pxh, (const __half*)pxl, (const __half*)pwh,
            (float*)pu, (__half*)pvh, (__half*)pvl, ntn);
    }
    // GEMM2: [32768,1024] @ [1024,1024]^T -> cand (fp32)
    {
        int ntm = MROWS / BM, ntn = DD / BN;       // 128, 8
        gemm_mma<1><<<ntm * ntn, NTHREADS, SMEM_TOTAL>>>(
            (const __half*)pvh, (const __half*)pvl, (const __half*)psh,
            (float*)pc, nullptr, nullptr, ntn);
    }

    // scan over T (y written in-place into g_c), then LN
    scan_kernel<<<(BB * DD) / 256, 256>>>();
    ln_kernel<<<MROWS, 256>>>(gamma, beta, out);
}

// round 8
// speedup vs baseline: 4.2164x; 1.1146x over previous
#include <cuda_runtime.h>
#include <cuda_fp16.h>
#include <math.h>
#include <stdint.h>

#define BB 16
#define TT 2048
#define DD 1024
#define MROWS (BB * TT)       // 32768
#define LN_EPS 1e-5f

// ---- GEMM tiling ----
#define BM 128
#define BN 128
#define BK 64                  // fp16 elems per k-chunk (4 kk-steps of 16)
#define NSTAGE 2
#define NTHREADS 256
#define ROWB 144               // 128B data + 16B pad (conflict-free ldmatrix)
#define A_HI_OFF 0
#define A_LO_OFF (BM * ROWB)                     // 18432
#define B_HI_OFF (2 * BM * ROWB)                 // 36864
#define STAGE_B  (2 * BM * ROWB + BN * ROWB)     // 55296
#define SMEM_TOTAL (NSTAGE * STAGE_B)            // 110592 -> 2 CTAs/SM
#define GROUP_M 16

// ---- scratch (__device__ globals; no cudaMalloc allowed) ----
__device__ __half g_xhi[(size_t)MROWS * DD];
__device__ __half g_xlo[(size_t)MROWS * DD];
__device__ __half g_wh [(size_t)2 * DD * DD];    // W_in fp16
__device__ __half g_sh [(size_t)DD * DD];        // W_state fp16
__device__ __half g_vhi[(size_t)MROWS * DD];
__device__ __half g_vlo[(size_t)MROWS * DD];
__device__ float g_u[(size_t)MROWS * DD];
__device__ float g_c[(size_t)MROWS * DD];

// ============================ device helpers ============================
__device__ __forceinline__ uint32_t smem_u32(const void* p) {
    uint32_t a;
    asm("{ .reg .u64 t; cvta.to.shared.u64 t, %1; cvt.u32.u64 %0, t; }" : "=r"(a) : "l"(p));
    return a;
}
__device__ __forceinline__ void cp16(uint32_t dst, const void* src) {
    asm volatile("cp.async.cg.shared.global [%0], [%1], 16;" :: "r"(dst), "l"(src));
}
__device__ __forceinline__ void cp_commit() {
    asm volatile("cp.async.commit_group;" ::: "memory");
}
template <int N>
__device__ __forceinline__ void cp_wait() {
    asm volatile("cp.async.wait_group %0;" :: "n"(N) : "memory");
}
__device__ __forceinline__ void ldsm4(uint32_t* r, uint32_t a) {
    asm volatile("ldmatrix.sync.aligned.m8n8.x4.shared.b16 {%0,%1,%2,%3}, [%4];"
                 : "=r"(r[0]), "=r"(r[1]), "=r"(r[2]), "=r"(r[3]) : "r"(a));
}
__device__ __forceinline__ void mma16816(float* c, const uint32_t* a, const uint32_t* b) {
    asm volatile(
        "mma.sync.aligned.m16n8k16.row.col.f32.f16.f16.f32 "
        "{%0,%1,%2,%3},{%4,%5,%6,%7},{%8,%9},{%0,%1,%2,%3};"
        : "+f"(c[0]), "+f"(c[1]), "+f"(c[2]), "+f"(c[3])
        : "r"(a[0]), "r"(a[1]), "r"(a[2]), "r"(a[3]), "r"(b[0]), "r"(b[1]));
}

// ============================ conversions ============================
// fp32 -> fp16 hi + lo residual
__global__ __launch_bounds__(256) void split_kernel(
    const float* __restrict__ src, __half* __restrict__ hi,
    __half* __restrict__ lo, int n)
{
    int i = (blockIdx.x * blockDim.x + threadIdx.x) * 4;
    if (i < n) {
        float4 v = *(const float4*)(src + i);
        float vv[4] = {v.x, v.y, v.z, v.w};
        unsigned short hb[4], lb[4];
#pragma unroll
        for (int e = 0; e < 4; e++) {
            __half h = __float2half_rn(vv[e]);
            float r = vv[e] - __half2float(h);
            hb[e] = __half_as_ushort(h);
            lb[e] = __half_as_ushort(__float2half_rn(r));
        }
        *(uint2*)(hi + i) = make_uint2((uint32_t)hb[0] | ((uint32_t)hb[1] << 16),
                                       (uint32_t)hb[2] | ((uint32_t)hb[3] << 16));
        *(uint2*)(lo + i) = make_uint2((uint32_t)lb[0] | ((uint32_t)lb[1] << 16),
                                       (uint32_t)lb[2] | ((uint32_t)lb[3] << 16));
    }
}

// fp32 -> fp16 (single)
__global__ __launch_bounds__(256) void conv_kernel(
    const float* __restrict__ src, __half* __restrict__ dst, int n)
{
    int i = (blockIdx.x * blockDim.x + threadIdx.x) * 4;
    if (i < n) {
        float4 v = *(const float4*)(src + i);
        unsigned short hb[4];
        hb[0] = __half_as_ushort(__float2half_rn(v.x));
        hb[1] = __half_as_ushort(__float2half_rn(v.y));
        hb[2] = __half_as_ushort(__float2half_rn(v.z));
        hb[3] = __half_as_ushort(__float2half_rn(v.w));
        *(uint2*)(dst + i) = make_uint2((uint32_t)hb[0] | ((uint32_t)hb[1] << 16),
                                        (uint32_t)hb[2] | ((uint32_t)hb[3] << 16));
    }
}

// ============================ fp16x2 mma.sync GEMM ============================
// C[BM,BN] tile of A @ B^T.  A:[M,K] fp16 hi/lo row-major, B:[N,K] fp16 row-major.
// acc = Ahi@B^T + Alo@B^T  (B residual dropped: ~2.7e-4 rel, under 1e-3 gate)
// 256 threads: 8 warps = 2 m-slices (64) x 4 n-slices (32). 2 CTAs/SM.
// MODE 0: GEMM1 — gate tiles (bn<DD): outF = sigmoid(acc) (u);
//                 value tiles: (ohi,olo) = fp16 hi/lo split of acc (vx).
// MODE 1: GEMM2 — outF = acc (cand).
template <int MODE>
__global__ __launch_bounds__(NTHREADS, 2)
void gemm_mma(const __half* __restrict__ Ahi, const __half* __restrict__ Alo,
              const __half* __restrict__ Bh,
              float* __restrict__ outF,
              __half* __restrict__ ohi, __half* __restrict__ olo,
              int ntn)
{
    extern __shared__ char smem[];
    const uint32_t sb = smem_u32(smem);
    const int tid = threadIdx.x;
    const int wid = tid >> 5, lane = tid & 31;

    // CTA swizzle: GROUP_M m-tiles per n-sweep for L2 reuse
    int per_group = GROUP_M * ntn;
    int group = blockIdx.x / per_group;
    int rem = blockIdx.x % per_group;
    const int bm = (group * GROUP_M + (rem % GROUP_M)) * BM;
    const int bn = (rem / GROUP_M) * BN;

    const int wm = wid & 1;   // 2 m-slices of 64
    const int wn = wid >> 1;  // 4 n-slices of 32

    // per-thread ldmatrix smem offsets (stage-invariant; kk adds kk*32 bytes)
    uint32_t offA[4], offB[2];
#pragma unroll
    for (int mf = 0; mf < 4; mf++)
        offA[mf] = (uint32_t)(wm * 64 + mf * 16 + (lane & 15)) * ROWB + (lane >> 4) * 16;
#pragma unroll
    for (int p = 0; p < 2; p++)
        offB[p] = (uint32_t)(wn * 32 + p * 16 + ((lane >> 4) & 1) * 8 + (lane & 7)) * ROWB
                  + ((lane >> 3) & 1) * 16;

    float acc[4][4][4];
#pragma unroll
    for (int a = 0; a < 4; a++)
#pragma unroll
        for (int b = 0; b < 4; b++)
#pragma unroll
            for (int e = 0; e < 4; e++) acc[a][b][e] = 0.f;

    // per-stage loads: A hi+lo = 8 cp/thread (4 j's), B = 4 cp/thread (4 j's); halves.
    auto load_half = [&](int kc, int half) {
        uint32_t base = sb + (uint32_t)(kc % NSTAGE) * STAGE_B;
        int k0 = kc * BK;
#pragma unroll
        for (int j = 0; j < 2; j++) {
            int ch = tid + (half * 2 + j) * NTHREADS;   // [0, 1024)
            int row = ch >> 3, kc8 = ch & 7;
            uint32_t doff = (uint32_t)row * ROWB + kc8 * 16;
            size_t ga = (size_t)(bm + row) * DD + k0 + kc8 * 8;
            cp16(base + A_HI_OFF + doff, Ahi + ga);
            cp16(base + A_LO_OFF + doff, Alo + ga);
            size_t gb = (size_t)(bn + row) * DD + k0 + kc8 * 8;
            cp16(base + B_HI_OFF + doff, Bh + gb);
        }
    };

    load_half(0, 0);
    load_half(0, 1);
    cp_commit();

    const int NKC = DD / BK;   // 16
    for (int kc = 0; kc < NKC; kc++) {
        cp_wait<0>();
        __syncthreads();                     // stage kc visible; all warps done with other buffer

        uint32_t base = sb + (uint32_t)(kc % NSTAGE) * STAGE_B;
#pragma unroll
        for (int kk = 0; kk < 4; kk++) {
            uint32_t ah[4][4], al[4][4], bh[2][4];
            // front-load all operands (10 ldsm)
#pragma unroll
            for (int mf = 0; mf < 4; mf++) {
                ldsm4(ah[mf], base + A_HI_OFF + offA[mf] + kk * 32);
                ldsm4(al[mf], base + A_LO_OFF + offA[mf] + kk * 32);
            }
#pragma unroll
            for (int p = 0; p < 2; p++)
                ldsm4(bh[p], base + B_HI_OFF + offB[p] + kk * 32);
            // spread next-stage cp.async issue into the middle of the chunk
            if (kc + 1 < NKC) {
                if (kk == 0) load_half(kc + 1, 0);
                if (kk == 1) { load_half(kc + 1, 1); cp_commit(); }
            }
            // 32 mma, uninterrupted
#pragma unroll
            for (int mf = 0; mf < 4; mf++) {
#pragma unroll
                for (int nf = 0; nf < 4; nf++) {
                    const uint32_t* b2 = &bh[nf >> 1][(nf & 1) * 2];
                    mma16816(acc[mf][nf], ah[mf], b2);
                    mma16816(acc[mf][nf], al[mf], b2);
                }
            }
        }
    }

    // ---- epilogue ----
    const int r0 = bm + wm * 64 + (lane >> 2);
    const int c0 = bn + wn * 32 + (lane & 3) * 2;
    const bool gate = (MODE == 0) && (bn < DD);

#pragma unroll
    for (int mf = 0; mf < 4; mf++) {
        int r = r0 + mf * 16;
#pragma unroll
        for (int nf = 0; nf < 4; nf++) {
            int c = c0 + nf * 8;
            float* a = acc[mf][nf];
            if (MODE == 1) {
                *(float2*)(outF + (size_t)r * DD + c)       = make_float2(a[0], a[1]);
                *(float2*)(outF + (size_t)(r + 8) * DD + c) = make_float2(a[2], a[3]);
            } else if (gate) {
                float2 s0, s1;
                s0.x = 1.f / (1.f + __expf(-a[0]));
                s0.y = 1.f / (1.f + __expf(-a[1]));
                s1.x = 1.f / (1.f + __expf(-a[2]));
                s1.y = 1.f / (1.f + __expf(-a[3]));
                *(float2*)(outF + (size_t)r * DD + c)       = s0;
                *(float2*)(outF + (size_t)(r + 8) * DD + c) = s1;
            } else {
                int cc = c - DD;
                unsigned short hb2[4], lb2[4];
#pragma unroll
                for (int e = 0; e < 4; e++) {
                    __half h = __float2half_rn(a[e]);
                    float rr = a[e] - __half2float(h);
                    hb2[e] = __half_as_ushort(h);
                    lb2[e] = __half_as_ushort(__float2half_rn(rr));
                }
                *(uint32_t*)(ohi + (size_t)r * DD + cc)       = (uint32_t)hb2[0] | ((uint32_t)hb2[1] << 16);
                *(uint32_t*)(ohi + (size_t)(r + 8) * DD + cc) = (uint32_t)hb2[2] | ((uint32_t)hb2[3] << 16);
                *(uint32_t*)(olo + (size_t)r * DD + cc)       = (uint32_t)lb2[0] | ((uint32_t)lb2[1] << 16);
                *(uint32_t*)(olo + (size_t)(r + 8) * DD + cc) = (uint32_t)lb2[2] | ((uint32_t)lb2[3] << 16);
            }
        }
    }
}

// ============================ scan (diagonal recurrence) ============================
// h_t = u*h + (1-u)*c = fma(u, h-c, c). Reads g_u, g_c; writes y in-place into g_c.
__global__ __launch_bounds__(256) void scan_kernel()
{
    int idx = blockIdx.x * blockDim.x + threadIdx.x;   // 0 .. B*D-1
    int b = idx >> 10;
    int d = idx & (DD - 1);
    float* up = g_u + (size_t)b * TT * DD + d;
    float* cp = g_c + (size_t)b * TT * DD + d;
    float h = 0.f;
    for (int t = 0; t < TT; t += 8) {
        float uu[8], cc[8];
#pragma unroll
        for (int j = 0; j < 8; j++) {
            uu[j] = up[(size_t)(t + j) * DD];
            cc[j] = cp[(size_t)(t + j) * DD];
        }
#pragma unroll
        for (int j = 0; j < 8; j++) {
            h = fmaf(uu[j], h - cc[j], cc[j]);
            cc[j] = h;
        }
#pragma unroll
        for (int j = 0; j < 8; j++) cp[(size_t)(t + j) * DD] = cc[j];
    }
}

// ============================ LayerNorm ============================
__global__ __launch_bounds__(256) void ln_kernel(const float* __restrict__ gamma,
                                                 const float* __restrict__ beta,
                                                 float* __restrict__ out)
{
    int row = blockIdx.x;
    int t = threadIdx.x;
    const float4* yr = (const float4*)(g_c + (size_t)row * DD);
    float4 v = yr[t];
    float s = v.x + v.y + v.z + v.w;
    float q = v.x * v.x + v.y * v.y + v.z * v.z + v.w * v.w;

#pragma unroll
    for (int o = 16; o; o >>= 1) {
        s += __shfl_xor_sync(0xFFFFFFFFu, s, o);
        q += __shfl_xor_sync(0xFFFFFFFFu, q, o);
    }
    __shared__ float sw[8], qw[8];
    __shared__ float mu_s, inv_s;
    int w = t >> 5, l = t & 31;
    if (l == 0) { sw[w] = s; qw[w] = q; }
    __syncthreads();
    if (t == 0) {
        float S = 0.f, Q = 0.f;
#pragma unroll
        for (int i = 0; i < 8; i++) { S += sw[i]; Q += qw[i]; }
        float mu = S * (1.f / DD);
        float var = Q * (1.f / DD) - mu * mu;
        mu_s = mu;
        inv_s = rsqrtf(var + LN_EPS);
    }
    __syncthreads();
    float mu = mu_s, inv = inv_s;

    const float4* g4 = (const float4*)gamma;
    const float4* b4 = (const float4*)beta;
    float4 gv = g4[t], bv = b4[t];
    float4 o;
    o.x = (v.x - mu) * inv * gv.x + bv.x;
    o.y = (v.y - mu) * inv * gv.y + bv.y;
    o.z = (v.z - mu) * inv * gv.z + bv.z;
    o.w = (v.w - mu) * inv * gv.w + bv.w;
    ((float4*)(out + (size_t)row * DD))[t] = o;
}

// ============================ host ============================
extern "C" void kernel_launch(void* const* d_in, const int* in_sizes, int n_in,
                              void* d_out, int out_size)
{
    const float* x       = (const float*)d_in[0];
    const float* W_in    = (const float*)d_in[1];
    const float* W_state = (const float*)d_in[2];
    const float* gamma   = (const float*)d_in[3];
    const float* beta    = (const float*)d_in[4];
    float* out = (float*)d_out;

    void *pxh, *pxl, *pwh, *psh, *pvh, *pvl, *pu, *pc;
    cudaGetSymbolAddress(&pxh, g_xhi); cudaGetSymbolAddress(&pxl, g_xlo);
    cudaGetSymbolAddress(&pwh, g_wh);  cudaGetSymbolAddress(&psh, g_sh);
    cudaGetSymbolAddress(&pvh, g_vhi); cudaGetSymbolAddress(&pvl, g_vlo);
    cudaGetSymbolAddress(&pu,  g_u);   cudaGetSymbolAddress(&pc,  g_c);

    cudaFuncSetAttribute(gemm_mma<0>, cudaFuncAttributeMaxDynamicSharedMemorySize, SMEM_TOTAL);
    cudaFuncSetAttribute(gemm_mma<1>, cudaFuncAttributeMaxDynamicSharedMemorySize, SMEM_TOTAL);

    // conversions
    { int n = MROWS * DD;  split_kernel<<<(n / 4 + 255) / 256, 256>>>(x, (__half*)pxh, (__half*)pxl, n); }
    { int n = 2 * DD * DD; conv_kernel<<<(n / 4 + 255) / 256, 256>>>(W_in, (__half*)pwh, n); }
    { int n = DD * DD;     conv_kernel<<<(n / 4 + 255) / 256, 256>>>(W_state, (__half*)psh, n); }

    // GEMM1: [32768,1024] @ [2048,1024]^T -> u (sigmoid fp32) + vx (fp16 hi/lo)
    {
        int ntm = MROWS / BM, ntn = 2 * DD / BN;   // 256, 16
        gemm_mma<0><<<ntm * ntn, NTHREADS, SMEM_TOTAL>>>(
            (const __half*)pxh, (const __half*)pxl, (const __half*)pwh,
            (float*)pu, (__half*)pvh, (__half*)pvl, ntn);
    }
    // GEMM2: [32768,1024] @ [1024,1024]^T -> cand (fp32)
    {
        int ntm = MROWS / BM, ntn = DD / BN;       // 256, 8
        gemm_mma<1><<<ntm * ntn, NTHREADS, SMEM_TOTAL>>>(
            (const __half*)pvh, (const __half*)pvl, (const __half*)psh,
            (float*)pc, nullptr, nullptr, ntn);
    }

    // scan over T (y written in-place into g_c), then LN
    scan_kernel<<<(BB * DD) / 256, 256>>>();
    ln_kernel<<<MROWS, 256>>>(gamma, beta, out);
}

// round 9
// speedup vs baseline: 4.8999x; 1.1621x over previous
#include <cuda_runtime.h>
#include <cuda_fp16.h>
#include <math.h>
#include <stdint.h>

#define BB 16
#define TT 2048
#define DD 1024
#define MROWS (BB * TT)       // 32768
#define LN_EPS 1e-5f

// ---- GEMM tiling ----
#define BM 128
#define BN 128
#define BK 64                  // fp16 elems per k-chunk (4 kk-steps of 16)
#define NSTAGE 2
#define NTHREADS 256
#define ROWB 144               // 128B data + 16B pad (conflict-free ldmatrix)
#define A_HI_OFF 0
#define A_LO_OFF (BM * ROWB)                     // 18432
#define B_HI_OFF (2 * BM * ROWB)                 // 36864
#define STAGE_B  (2 * BM * ROWB + BN * ROWB)     // 55296
#define SMEM_TOTAL (NSTAGE * STAGE_B)            // 110592 -> 2 CTAs/SM
#define GROUP_M 16

// ---- scratch (__device__ globals; no cudaMalloc allowed) ----
__device__ __half g_xhi[(size_t)MROWS * DD];
__device__ __half g_xlo[(size_t)MROWS * DD];
__device__ __half g_wh [(size_t)2 * DD * DD];    // W_in fp16
__device__ __half g_sh [(size_t)DD * DD];        // W_state fp16
__device__ __half g_vhi[(size_t)MROWS * DD];     // vx fp16 (single precision operand)
__device__ float g_u[(size_t)MROWS * DD];
__device__ float g_c[(size_t)MROWS * DD];

// ============================ device helpers ============================
__device__ __forceinline__ uint32_t smem_u32(const void* p) {
    uint32_t a;
    asm("{ .reg .u64 t; cvta.to.shared.u64 t, %1; cvt.u32.u64 %0, t; }" : "=r"(a) : "l"(p));
    return a;
}
__device__ __forceinline__ void cp16(uint32_t dst, const void* src) {
    asm volatile("cp.async.cg.shared.global [%0], [%1], 16;" :: "r"(dst), "l"(src));
}
__device__ __forceinline__ void cp_commit() {
    asm volatile("cp.async.commit_group;" ::: "memory");
}
template <int N>
__device__ __forceinline__ void cp_wait() {
    asm volatile("cp.async.wait_group %0;" :: "n"(N) : "memory");
}
__device__ __forceinline__ void ldsm4(uint32_t* r, uint32_t a) {
    asm volatile("ldmatrix.sync.aligned.m8n8.x4.shared.b16 {%0,%1,%2,%3}, [%4];"
                 : "=r"(r[0]), "=r"(r[1]), "=r"(r[2]), "=r"(r[3]) : "r"(a));
}
__device__ __forceinline__ void mma16816(float* c, const uint32_t* a, const uint32_t* b) {
    asm volatile(
        "mma.sync.aligned.m16n8k16.row.col.f32.f16.f16.f32 "
        "{%0,%1,%2,%3},{%4,%5,%6,%7},{%8,%9},{%0,%1,%2,%3};"
        : "+f"(c[0]), "+f"(c[1]), "+f"(c[2]), "+f"(c[3])
        : "r"(a[0]), "r"(a[1]), "r"(a[2]), "r"(a[3]), "r"(b[0]), "r"(b[1]));
}

// ============================ conversions ============================
// fp32 -> fp16 hi + lo residual
__global__ __launch_bounds__(256) void split_kernel(
    const float* __restrict__ src, __half* __restrict__ hi,
    __half* __restrict__ lo, int n)
{
    int i = (blockIdx.x * blockDim.x + threadIdx.x) * 4;
    if (i < n) {
        float4 v = *(const float4*)(src + i);
        float vv[4] = {v.x, v.y, v.z, v.w};
        unsigned short hb[4], lb[4];
#pragma unroll
        for (int e = 0; e < 4; e++) {
            __half h = __float2half_rn(vv[e]);
            float r = vv[e] - __half2float(h);
            hb[e] = __half_as_ushort(h);
            lb[e] = __half_as_ushort(__float2half_rn(r));
        }
        *(uint2*)(hi + i) = make_uint2((uint32_t)hb[0] | ((uint32_t)hb[1] << 16),
                                       (uint32_t)hb[2] | ((uint32_t)hb[3] << 16));
        *(uint2*)(lo + i) = make_uint2((uint32_t)lb[0] | ((uint32_t)lb[1] << 16),
                                       (uint32_t)lb[2] | ((uint32_t)lb[3] << 16));
    }
}

// fp32 -> fp16 (single)
__global__ __launch_bounds__(256) void conv_kernel(
    const float* __restrict__ src, __half* __restrict__ dst, int n)
{
    int i = (blockIdx.x * blockDim.x + threadIdx.x) * 4;
    if (i < n) {
        float4 v = *(const float4*)(src + i);
        unsigned short hb[4];
        hb[0] = __half_as_ushort(__float2half_rn(v.x));
        hb[1] = __half_as_ushort(__float2half_rn(v.y));
        hb[2] = __half_as_ushort(__float2half_rn(v.z));
        hb[3] = __half_as_ushort(__float2half_rn(v.w));
        *(uint2*)(dst + i) = make_uint2((uint32_t)hb[0] | ((uint32_t)hb[1] << 16),
                                        (uint32_t)hb[2] | ((uint32_t)hb[3] << 16));
    }
}

// ============================ fp16 mma.sync GEMM ============================
// C[BM,BN] tile of A @ B^T.  A:[M,K] fp16 (hi[,lo]) row-major, B:[N,K] fp16 row-major.
// SPLIT_A=1: acc = Ahi@B^T + Alo@B^T ;  SPLIT_A=0: acc = A@B^T.
// 256 threads: 8 warps = 4 m-slices (32) x 2 n-slices (64). 2 CTAs/SM.
// MODE 0 (GEMM1): gate tiles (bn<DD): outF = sigmoid(acc) (u);
//                 value tiles: ohi = fp16(acc) (vx).
// MODE 1 (GEMM2): outF = acc (cand).
template <int MODE, int SPLIT_A>
__global__ __launch_bounds__(NTHREADS, 2)
void gemm_mma(const __half* __restrict__ Ahi, const __half* __restrict__ Alo,
              const __half* __restrict__ Bh,
              float* __restrict__ outF,
              __half* __restrict__ ohi,
              int ntn)
{
    extern __shared__ char smem[];
    const uint32_t sb = smem_u32(smem);
    const int tid = threadIdx.x;
    const int wid = tid >> 5, lane = tid & 31;

    // CTA swizzle: GROUP_M m-tiles per n-sweep for L2 reuse
    int per_group = GROUP_M * ntn;
    int group = blockIdx.x / per_group;
    int rem = blockIdx.x % per_group;
    const int bm = (group * GROUP_M + (rem % GROUP_M)) * BM;
    const int bn = (rem / GROUP_M) * BN;

    const int wm = wid & 3;   // 4 m-slices of 32
    const int wn = wid >> 2;  // 2 n-slices of 64

    // per-thread ldmatrix smem offsets (stage-invariant; kk adds kk*32 bytes)
    uint32_t offA[2], offB[4];
#pragma unroll
    for (int mf = 0; mf < 2; mf++)
        offA[mf] = (uint32_t)(wm * 32 + mf * 16 + (lane & 15)) * ROWB + (lane >> 4) * 16;
#pragma unroll
    for (int p = 0; p < 4; p++)
        offB[p] = (uint32_t)(wn * 64 + p * 16 + ((lane >> 4) & 1) * 8 + (lane & 7)) * ROWB
                  + ((lane >> 3) & 1) * 16;

    float acc[2][8][4];
#pragma unroll
    for (int a = 0; a < 2; a++)
#pragma unroll
        for (int b = 0; b < 8; b++)
#pragma unroll
            for (int e = 0; e < 4; e++) acc[a][b][e] = 0.f;

    // per-stage loads: A hi (=lo) 1024 chunks each, B 1024 chunks; 256 thr -> 4 slots
    auto load_half = [&](int kc, int half) {
        uint32_t base = sb + (uint32_t)(kc % NSTAGE) * STAGE_B;
        int k0 = kc * BK;
#pragma unroll
        for (int j = 0; j < 2; j++) {
            int ch = tid + (half * 2 + j) * NTHREADS;   // [0, 1024)
            int row = ch >> 3, kc8 = ch & 7;
            uint32_t doff = (uint32_t)row * ROWB + kc8 * 16;
            size_t ga = (size_t)(bm + row) * DD + k0 + kc8 * 8;
            cp16(base + A_HI_OFF + doff, Ahi + ga);
            if (SPLIT_A) cp16(base + A_LO_OFF + doff, Alo + ga);
            size_t gb = (size_t)(bn + row) * DD + k0 + kc8 * 8;
            cp16(base + B_HI_OFF + doff, Bh + gb);
        }
    };

    load_half(0, 0);
    load_half(0, 1);
    cp_commit();

    const int NKC = DD / BK;   // 16
    for (int kc = 0; kc < NKC; kc++) {
        cp_wait<0>();
        __syncthreads();                     // stage kc visible; all warps done with other buffer

        uint32_t base = sb + (uint32_t)(kc % NSTAGE) * STAGE_B;
#pragma unroll
        for (int kk = 0; kk < 4; kk++) {
            uint32_t ah[2][4], al[2][4], bh[4][4];
            // front-load all operands
#pragma unroll
            for (int mf = 0; mf < 2; mf++) {
                ldsm4(ah[mf], base + A_HI_OFF + offA[mf] + kk * 32);
                if (SPLIT_A) ldsm4(al[mf], base + A_LO_OFF + offA[mf] + kk * 32);
            }
#pragma unroll
            for (int p = 0; p < 4; p++)
                ldsm4(bh[p], base + B_HI_OFF + offB[p] + kk * 32);
            // spread next-stage cp.async issue into the middle of the chunk
            if (kc + 1 < NKC) {
                if (kk == 0) load_half(kc + 1, 0);
                if (kk == 1) { load_half(kc + 1, 1); cp_commit(); }
            }
            // mma block, uninterrupted
#pragma unroll
            for (int mf = 0; mf < 2; mf++) {
#pragma unroll
                for (int nf = 0; nf < 8; nf++) {
                    const uint32_t* b2 = &bh[nf >> 1][(nf & 1) * 2];
                    mma16816(acc[mf][nf], ah[mf], b2);
                    if (SPLIT_A) mma16816(acc[mf][nf], al[mf], b2);
                }
            }
        }
    }

    // ---- epilogue ----
    const int r0 = bm + wm * 32 + (lane >> 2);
    const int c0 = bn + wn * 64 + (lane & 3) * 2;
    const bool gate = (MODE == 0) && (bn < DD);

#pragma unroll
    for (int mf = 0; mf < 2; mf++) {
        int r = r0 + mf * 16;
#pragma unroll
        for (int nf = 0; nf < 8; nf++) {
            int c = c0 + nf * 8;
            float* a = acc[mf][nf];
            if (MODE == 1) {
                *(float2*)(outF + (size_t)r * DD + c)       = make_float2(a[0], a[1]);
                *(float2*)(outF + (size_t)(r + 8) * DD + c) = make_float2(a[2], a[3]);
            } else if (gate) {
                float2 s0, s1;
                s0.x = 1.f / (1.f + __expf(-a[0]));
                s0.y = 1.f / (1.f + __expf(-a[1]));
                s1.x = 1.f / (1.f + __expf(-a[2]));
                s1.y = 1.f / (1.f + __expf(-a[3]));
                *(float2*)(outF + (size_t)r * DD + c)       = s0;
                *(float2*)(outF + (size_t)(r + 8) * DD + c) = s1;
            } else {
                int cc = c - DD;
                unsigned short hb2[4];
#pragma unroll
                for (int e = 0; e < 4; e++)
                    hb2[e] = __half_as_ushort(__float2half_rn(a[e]));
                *(uint32_t*)(ohi + (size_t)r * DD + cc)       = (uint32_t)hb2[0] | ((uint32_t)hb2[1] << 16);
                *(uint32_t*)(ohi + (size_t)(r + 8) * DD + cc) = (uint32_t)hb2[2] | ((uint32_t)hb2[3] << 16);
            }
        }
    }
}

// ============================ scan (diagonal recurrence) ============================
// h_t = u*h + (1-u)*c = fma(u, h-c, c). Reads g_u, g_c; writes y in-place into g_c.
__global__ __launch_bounds__(256) void scan_kernel()
{
    int idx = blockIdx.x * blockDim.x + threadIdx.x;   // 0 .. B*D-1
    int b = idx >> 10;
    int d = idx & (DD - 1);
    float* up = g_u + (size_t)b * TT * DD + d;
    float* cp = g_c + (size_t)b * TT * DD + d;
    float h = 0.f;
    for (int t = 0; t < TT; t += 16) {
        float uu[16], cc[16];
#pragma unroll
        for (int j = 0; j < 16; j++) {
            uu[j] = up[(size_t)(t + j) * DD];
            cc[j] = cp[(size_t)(t + j) * DD];
        }
#pragma unroll
        for (int j = 0; j < 16; j++) {
            h = fmaf(uu[j], h - cc[j], cc[j]);
            cc[j] = h;
        }
#pragma unroll
        for (int j = 0; j < 16; j++) cp[(size_t)(t + j) * DD] = cc[j];
    }
}

// ============================ LayerNorm ============================
__global__ __launch_bounds__(256) void ln_kernel(const float* __restrict__ gamma,
                                                 const float* __restrict__ beta,
                                                 float* __restrict__ out)
{
    int row = blockIdx.x;
    int t = threadIdx.x;
    const float4* yr = (const float4*)(g_c + (size_t)row * DD);
    float4 v = yr[t];
    float s = v.x + v.y + v.z + v.w;
    float q = v.x * v.x + v.y * v.y + v.z * v.z + v.w * v.w;

#pragma unroll
    for (int o = 16; o; o >>= 1) {
        s += __shfl_xor_sync(0xFFFFFFFFu, s, o);
        q += __shfl_xor_sync(0xFFFFFFFFu, q, o);
    }
    __shared__ float sw[8], qw[8];
    __shared__ float mu_s, inv_s;
    int w = t >> 5, l = t & 31;
    if (l == 0) { sw[w] = s; qw[w] = q; }
    __syncthreads();
    if (t == 0) {
        float S = 0.f, Q = 0.f;
#pragma unroll
        for (int i = 0; i < 8; i++) { S += sw[i]; Q += qw[i]; }
        float mu = S * (1.f / DD);
        float var = Q * (1.f / DD) - mu * mu;
        mu_s = mu;
        inv_s = rsqrtf(var + LN_EPS);
    }
    __syncthreads();
    float mu = mu_s, inv = inv_s;

    const float4* g4 = (const float4*)gamma;
    const float4* b4 = (const float4*)beta;
    float4 gv = g4[t], bv = b4[t];
    float4 o;
    o.x = (v.x - mu) * inv * gv.x + bv.x;
    o.y = (v.y - mu) * inv * gv.y + bv.y;
    o.z = (v.z - mu) * inv * gv.z + bv.z;
    o.w = (v.w - mu) * inv * gv.w + bv.w;
    ((float4*)(out + (size_t)row * DD))[t] = o;
}

// ============================ host ============================
extern "C" void kernel_launch(void* const* d_in, const int* in_sizes, int n_in,
                              void* d_out, int out_size)
{
    const float* x       = (const float*)d_in[0];
    const float* W_in    = (const float*)d_in[1];
    const float* W_state = (const float*)d_in[2];
    const float* gamma   = (const float*)d_in[3];
    const float* beta    = (const float*)d_in[4];
    float* out = (float*)d_out;

    void *pxh, *pxl, *pwh, *psh, *pvh, *pu, *pc;
    cudaGetSymbolAddress(&pxh, g_xhi); cudaGetSymbolAddress(&pxl, g_xlo);
    cudaGetSymbolAddress(&pwh, g_wh);  cudaGetSymbolAddress(&psh, g_sh);
    cudaGetSymbolAddress(&pvh, g_vhi);
    cudaGetSymbolAddress(&pu,  g_u);   cudaGetSymbolAddress(&pc,  g_c);

    cudaFuncSetAttribute((const void*)gemm_mma<0, 1>, cudaFuncAttributeMaxDynamicSharedMemorySize, SMEM_TOTAL);
    cudaFuncSetAttribute((const void*)gemm_mma<1, 0>, cudaFuncAttributeMaxDynamicSharedMemorySize, SMEM_TOTAL);

    // conversions
    { int n = MROWS * DD;  split_kernel<<<(n / 4 + 255) / 256, 256>>>(x, (__half*)pxh, (__half*)pxl, n); }
    { int n = 2 * DD * DD; conv_kernel<<<(n / 4 + 255) / 256, 256>>>(W_in, (__half*)pwh, n); }
    { int n = DD * DD;     conv_kernel<<<(n / 4 + 255) / 256, 256>>>(W_state, (__half*)psh, n); }

    // GEMM1: [32768,1024] @ [2048,1024]^T -> u (sigmoid fp32) + vx (fp16)
    {
        int ntm = MROWS / BM, ntn = 2 * DD / BN;   // 256, 16
        gemm_mma<0, 1><<<ntm * ntn, NTHREADS, SMEM_TOTAL>>>(
            (const __half*)pxh, (const __half*)pxl, (const __half*)pwh,
            (float*)pu, (__half*)pvh, ntn);
    }
    // GEMM2: [32768,1024] @ [1024,1024]^T -> cand (fp32), single-precision A
    {
        int ntm = MROWS / BM, ntn = DD / BN;       // 256, 8
        gemm_mma<1, 0><<<ntm * ntn, NTHREADS, SMEM_TOTAL>>>(
            (const __half*)pvh, nullptr, (const __half*)psh,
            (float*)pc, nullptr, ntn);
    }

    // scan over T (y written in-place into g_c), then LN
    scan_kernel<<<(BB * DD) / 256, 256>>>();
    ln_kernel<<<MROWS, 256>>>(gamma, beta, out);
}

// round 10
// speedup vs baseline: 5.3812x; 1.0982x over previous
#include <cuda_runtime.h>
#include <cuda_fp16.h>
#include <math.h>
#include <stdint.h>

#define BB 16
#define TT 2048
#define DD 1024
#define MROWS (BB * TT)       // 32768
#define LN_EPS 1e-5f

// ---- GEMM tiling ----
#define BM 128
#define BN 128
#define BK 64                  // fp16 elems per k-chunk (4 kk-steps of 16)
#define NSTAGE 2
#define NTHREADS 256
#define ROWB 144               // 128B data + 16B pad (conflict-free ldmatrix)
#define A_HI_OFF 0
#define A_LO_OFF (BM * ROWB)                     // 18432
#define B_HI_OFF (2 * BM * ROWB)                 // 36864
#define STAGE_B  (2 * BM * ROWB + BN * ROWB)     // 55296
#define SMEM_TOTAL (NSTAGE * STAGE_B)            // 110592 -> 2 CTAs/SM
#define GROUP_M 16

// ---- scratch (__device__ globals; no cudaMalloc allowed) ----
__device__ __half g_xhi[(size_t)MROWS * DD];
__device__ __half g_xlo[(size_t)MROWS * DD];
__device__ __half g_wh [(size_t)2 * DD * DD];    // W_in fp16
__device__ __half g_sh [(size_t)DD * DD];        // W_state fp16
__device__ __half g_vhi[(size_t)MROWS * DD];     // vx fp16
__device__ float g_u[(size_t)MROWS * DD];
__device__ float g_c[(size_t)MROWS * DD];

// ============================ device helpers ============================
__device__ __forceinline__ uint32_t smem_u32(const void* p) {
    uint32_t a;
    asm("{ .reg .u64 t; cvta.to.shared.u64 t, %1; cvt.u32.u64 %0, t; }" : "=r"(a) : "l"(p));
    return a;
}
__device__ __forceinline__ void cp16(uint32_t dst, const void* src) {
    asm volatile("cp.async.cg.shared.global [%0], [%1], 16;" :: "r"(dst), "l"(src));
}
__device__ __forceinline__ void cp_commit() {
    asm volatile("cp.async.commit_group;" ::: "memory");
}
template <int N>
__device__ __forceinline__ void cp_wait() {
    asm volatile("cp.async.wait_group %0;" :: "n"(N) : "memory");
}
__device__ __forceinline__ void ldsm4(uint32_t* r, uint32_t a) {
    asm volatile("ldmatrix.sync.aligned.m8n8.x4.shared.b16 {%0,%1,%2,%3}, [%4];"
                 : "=r"(r[0]), "=r"(r[1]), "=r"(r[2]), "=r"(r[3]) : "r"(a));
}
__device__ __forceinline__ void mma16816(float* c, const uint32_t* a, const uint32_t* b) {
    asm volatile(
        "mma.sync.aligned.m16n8k16.row.col.f32.f16.f16.f32 "
        "{%0,%1,%2,%3},{%4,%5,%6,%7},{%8,%9},{%0,%1,%2,%3};"
        : "+f"(c[0]), "+f"(c[1]), "+f"(c[2]), "+f"(c[3])
        : "r"(a[0]), "r"(a[1]), "r"(a[2]), "r"(a[3]), "r"(b[0]), "r"(b[1]));
}

// ============================ conversions ============================
// fp32 -> fp16 hi + lo residual
__global__ __launch_bounds__(256) void split_kernel(
    const float* __restrict__ src, __half* __restrict__ hi,
    __half* __restrict__ lo, int n)
{
    int i = (blockIdx.x * blockDim.x + threadIdx.x) * 4;
    if (i < n) {
        float4 v = *(const float4*)(src + i);
        float vv[4] = {v.x, v.y, v.z, v.w};
        unsigned short hb[4], lb[4];
#pragma unroll
        for (int e = 0; e < 4; e++) {
            __half h = __float2half_rn(vv[e]);
            float r = vv[e] - __half2float(h);
            hb[e] = __half_as_ushort(h);
            lb[e] = __half_as_ushort(__float2half_rn(r));
        }
        *(uint2*)(hi + i) = make_uint2((uint32_t)hb[0] | ((uint32_t)hb[1] << 16),
                                       (uint32_t)hb[2] | ((uint32_t)hb[3] << 16));
        *(uint2*)(lo + i) = make_uint2((uint32_t)lb[0] | ((uint32_t)lb[1] << 16),
                                       (uint32_t)lb[2] | ((uint32_t)lb[3] << 16));
    }
}

// fp32 -> fp16 (single)
__global__ __launch_bounds__(256) void conv_kernel(
    const float* __restrict__ src, __half* __restrict__ dst, int n)
{
    int i = (blockIdx.x * blockDim.x + threadIdx.x) * 4;
    if (i < n) {
        float4 v = *(const float4*)(src + i);
        unsigned short hb[4];
        hb[0] = __half_as_ushort(__float2half_rn(v.x));
        hb[1] = __half_as_ushort(__float2half_rn(v.y));
        hb[2] = __half_as_ushort(__float2half_rn(v.z));
        hb[3] = __half_as_ushort(__float2half_rn(v.w));
        *(uint2*)(dst + i) = make_uint2((uint32_t)hb[0] | ((uint32_t)hb[1] << 16),
                                        (uint32_t)hb[2] | ((uint32_t)hb[3] << 16));
    }
}

// ============================ fp16 mma.sync GEMM ============================
// C[BM,BN] tile of A @ B^T.  A:[M,K] fp16 (hi[,lo]) row-major, B:[N,K] fp16 row-major.
// SPLIT_A=1: acc = Ahi@B^T + Alo@B^T ;  SPLIT_A=0: acc = A@B^T.
// 256 threads: 8 warps = 4 m-slices (32) x 2 n-slices (64). 2 CTAs/SM.
// MODE 0: outF = sigmoid(acc)   (gate half of GEMM1 -> u)
// MODE 1: outF = acc            (GEMM2 -> cand)
// MODE 2: ohi  = fp16(acc)      (value half of GEMM1 -> vx)
template <int MODE, int SPLIT_A>
__global__ __launch_bounds__(NTHREADS, 2)
void gemm_mma(const __half* __restrict__ Ahi, const __half* __restrict__ Alo,
              const __half* __restrict__ Bh,
              float* __restrict__ outF,
              __half* __restrict__ ohi,
              int ntn)
{
    extern __shared__ char smem[];
    const uint32_t sb = smem_u32(smem);
    const int tid = threadIdx.x;
    const int wid = tid >> 5, lane = tid & 31;

    // CTA swizzle: GROUP_M m-tiles per n-sweep for L2 reuse
    int per_group = GROUP_M * ntn;
    int group = blockIdx.x / per_group;
    int rem = blockIdx.x % per_group;
    const int bm = (group * GROUP_M + (rem % GROUP_M)) * BM;
    const int bn = (rem / GROUP_M) * BN;

    const int wm = wid & 3;   // 4 m-slices of 32
    const int wn = wid >> 2;  // 2 n-slices of 64

    // per-thread ldmatrix smem offsets (stage-invariant; kk adds kk*32 bytes)
    uint32_t offA[2], offB[4];
#pragma unroll
    for (int mf = 0; mf < 2; mf++)
        offA[mf] = (uint32_t)(wm * 32 + mf * 16 + (lane & 15)) * ROWB + (lane >> 4) * 16;
#pragma unroll
    for (int p = 0; p < 4; p++)
        offB[p] = (uint32_t)(wn * 64 + p * 16 + ((lane >> 4) & 1) * 8 + (lane & 7)) * ROWB
                  + ((lane >> 3) & 1) * 16;

    float acc[2][8][4];
#pragma unroll
    for (int a = 0; a < 2; a++)
#pragma unroll
        for (int b = 0; b < 8; b++)
#pragma unroll
            for (int e = 0; e < 4; e++) acc[a][b][e] = 0.f;

    auto load_half = [&](int kc, int half) {
        uint32_t base = sb + (uint32_t)(kc % NSTAGE) * STAGE_B;
        int k0 = kc * BK;
#pragma unroll
        for (int j = 0; j < 2; j++) {
            int ch = tid + (half * 2 + j) * NTHREADS;   // [0, 1024)
            int row = ch >> 3, kc8 = ch & 7;
            uint32_t doff = (uint32_t)row * ROWB + kc8 * 16;
            size_t ga = (size_t)(bm + row) * DD + k0 + kc8 * 8;
            cp16(base + A_HI_OFF + doff, Ahi + ga);
            if (SPLIT_A) cp16(base + A_LO_OFF + doff, Alo + ga);
            size_t gb = (size_t)(bn + row) * DD + k0 + kc8 * 8;
            cp16(base + B_HI_OFF + doff, Bh + gb);
        }
    };

    load_half(0, 0);
    load_half(0, 1);
    cp_commit();

    const int NKC = DD / BK;   // 16
    for (int kc = 0; kc < NKC; kc++) {
        cp_wait<0>();
        __syncthreads();                     // stage kc visible; all warps done with other buffer

        uint32_t base = sb + (uint32_t)(kc % NSTAGE) * STAGE_B;
#pragma unroll
        for (int kk = 0; kk < 4; kk++) {
            uint32_t ah[2][4], al[2][4], bh[4][4];
            // front-load all operands
#pragma unroll
            for (int mf = 0; mf < 2; mf++) {
                ldsm4(ah[mf], base + A_HI_OFF + offA[mf] + kk * 32);
                if (SPLIT_A) ldsm4(al[mf], base + A_LO_OFF + offA[mf] + kk * 32);
            }
#pragma unroll
            for (int p = 0; p < 4; p++)
                ldsm4(bh[p], base + B_HI_OFF + offB[p] + kk * 32);
            // spread next-stage cp.async issue into the middle of the chunk
            if (kc + 1 < NKC) {
                if (kk == 0) load_half(kc + 1, 0);
                if (kk == 1) { load_half(kc + 1, 1); cp_commit(); }
            }
            // mma block, uninterrupted
#pragma unroll
            for (int mf = 0; mf < 2; mf++) {
#pragma unroll
                for (int nf = 0; nf < 8; nf++) {
                    const uint32_t* b2 = &bh[nf >> 1][(nf & 1) * 2];
                    mma16816(acc[mf][nf], ah[mf], b2);
                    if (SPLIT_A) mma16816(acc[mf][nf], al[mf], b2);
                }
            }
        }
    }

    // ---- epilogue ----
    const int r0 = bm + wm * 32 + (lane >> 2);
    const int c0 = bn + wn * 64 + (lane & 3) * 2;

#pragma unroll
    for (int mf = 0; mf < 2; mf++) {
        int r = r0 + mf * 16;
#pragma unroll
        for (int nf = 0; nf < 8; nf++) {
            int c = c0 + nf * 8;
            float* a = acc[mf][nf];
            if (MODE == 1) {
                *(float2*)(outF + (size_t)r * DD + c)       = make_float2(a[0], a[1]);
                *(float2*)(outF + (size_t)(r + 8) * DD + c) = make_float2(a[2], a[3]);
            } else if (MODE == 0) {
                float2 s0, s1;
                s0.x = 1.f / (1.f + __expf(-a[0]));
                s0.y = 1.f / (1.f + __expf(-a[1]));
                s1.x = 1.f / (1.f + __expf(-a[2]));
                s1.y = 1.f / (1.f + __expf(-a[3]));
                *(float2*)(outF + (size_t)r * DD + c)       = s0;
                *(float2*)(outF + (size_t)(r + 8) * DD + c) = s1;
            } else {
                unsigned short hb2[4];
#pragma unroll
                for (int e = 0; e < 4; e++)
                    hb2[e] = __half_as_ushort(__float2half_rn(a[e]));
                *(uint32_t*)(ohi + (size_t)r * DD + c)       = (uint32_t)hb2[0] | ((uint32_t)hb2[1] << 16);
                *(uint32_t*)(ohi + (size_t)(r + 8) * DD + c) = (uint32_t)hb2[2] | ((uint32_t)hb2[3] << 16);
            }
        }
    }
}

// ============================ scan (diagonal recurrence) ============================
// h_t = u*h + (1-u)*c = fma(u, h-c, c). Reads g_u, g_c; writes y in-place into g_c.
__global__ __launch_bounds__(256) void scan_kernel()
{
    int idx = blockIdx.x * blockDim.x + threadIdx.x;   // 0 .. B*D-1
    int b = idx >> 10;
    int d = idx & (DD - 1);
    float* up = g_u + (size_t)b * TT * DD + d;
    float* cp = g_c + (size_t)b * TT * DD + d;
    float h = 0.f;
    for (int t = 0; t < TT; t += 16) {
        float uu[16], cc[16];
#pragma unroll
        for (int j = 0; j < 16; j++) {
            uu[j] = up[(size_t)(t + j) * DD];
            cc[j] = cp[(size_t)(t + j) * DD];
        }
#pragma unroll
        for (int j = 0; j < 16; j++) {
            h = fmaf(uu[j], h - cc[j], cc[j]);
            cc[j] = h;
        }
#pragma unroll
        for (int j = 0; j < 16; j++) cp[(size_t)(t + j) * DD] = cc[j];
    }
}

// ============================ LayerNorm ============================
__global__ __launch_bounds__(256) void ln_kernel(const float* __restrict__ gamma,
                                                 const float* __restrict__ beta,
                                                 float* __restrict__ out)
{
    int row = blockIdx.x;
    int t = threadIdx.x;
    const float4* yr = (const float4*)(g_c + (size_t)row * DD);
    float4 v = yr[t];
    float s = v.x + v.y + v.z + v.w;
    float q = v.x * v.x + v.y * v.y + v.z * v.z + v.w * v.w;

#pragma unroll
    for (int o = 16; o; o >>= 1) {
        s += __shfl_xor_sync(0xFFFFFFFFu, s, o);
        q += __shfl_xor_sync(0xFFFFFFFFu, q, o);
    }
    __shared__ float sw[8], qw[8];
    __shared__ float mu_s, inv_s;
    int w = t >> 5, l = t & 31;
    if (l == 0) { sw[w] = s; qw[w] = q; }
    __syncthreads();
    if (t == 0) {
        float S = 0.f, Q = 0.f;
#pragma unroll
        for (int i = 0; i < 8; i++) { S += sw[i]; Q += qw[i]; }
        float mu = S * (1.f / DD);
        float var = Q * (1.f / DD) - mu * mu;
        mu_s = mu;
        inv_s = rsqrtf(var + LN_EPS);
    }
    __syncthreads();
    float mu = mu_s, inv = inv_s;

    const float4* g4 = (const float4*)gamma;
    const float4* b4 = (const float4*)beta;
    float4 gv = g4[t], bv = b4[t];
    float4 o;
    o.x = (v.x - mu) * inv * gv.x + bv.x;
    o.y = (v.y - mu) * inv * gv.y + bv.y;
    o.z = (v.z - mu) * inv * gv.z + bv.z;
    o.w = (v.w - mu) * inv * gv.w + bv.w;
    ((float4*)(out + (size_t)row * DD))[t] = o;
}

// ============================ host ============================
extern "C" void kernel_launch(void* const* d_in, const int* in_sizes, int n_in,
                              void* d_out, int out_size)
{
    const float* x       = (const float*)d_in[0];
    const float* W_in    = (const float*)d_in[1];
    const float* W_state = (const float*)d_in[2];
    const float* gamma   = (const float*)d_in[3];
    const float* beta    = (const float*)d_in[4];
    float* out = (float*)d_out;

    void *pxh, *pxl, *pwh, *psh, *pvh, *pu, *pc;
    cudaGetSymbolAddress(&pxh, g_xhi); cudaGetSymbolAddress(&pxl, g_xlo);
    cudaGetSymbolAddress(&pwh, g_wh);  cudaGetSymbolAddress(&psh, g_sh);
    cudaGetSymbolAddress(&pvh, g_vhi);
    cudaGetSymbolAddress(&pu,  g_u);   cudaGetSymbolAddress(&pc,  g_c);

    cudaFuncSetAttribute((const void*)gemm_mma<0, 0>, cudaFuncAttributeMaxDynamicSharedMemorySize, SMEM_TOTAL);
    cudaFuncSetAttribute((const void*)gemm_mma<2, 1>, cudaFuncAttributeMaxDynamicSharedMemorySize, SMEM_TOTAL);
    cudaFuncSetAttribute((const void*)gemm_mma<1, 0>, cudaFuncAttributeMaxDynamicSharedMemorySize, SMEM_TOTAL);

    // conversions
    { int n = MROWS * DD;  split_kernel<<<(n / 4 + 255) / 256, 256>>>(x, (__half*)pxh, (__half*)pxl, n); }
    { int n = 2 * DD * DD; conv_kernel<<<(n / 4 + 255) / 256, 256>>>(W_in, (__half*)pwh, n); }
    { int n = DD * DD;     conv_kernel<<<(n / 4 + 255) / 256, 256>>>(W_state, (__half*)psh, n); }

    const int ntm = MROWS / BM;        // 256
    const int ntn = DD / BN;           // 8

    // GEMM1 gate half: x @ W_in[0:D]^T -> u = sigmoid (single-precision A)
    gemm_mma<0, 0><<<ntm * ntn, NTHREADS, SMEM_TOTAL>>>(
        (const __half*)pxh, nullptr, (const __half*)pwh,
        (float*)pu, nullptr, ntn);

    // GEMM1 value half: x @ W_in[D:2D]^T -> vx fp16 (split A)
    gemm_mma<2, 1><<<ntm * ntn, NTHREADS, SMEM_TOTAL>>>(
        (const __half*)pxh, (const __half*)pxl, (const __half*)pwh + (size_t)DD * DD,
        nullptr, (__half*)pvh, ntn);

    // GEMM2: vx @ W_state^T -> cand fp32 (single-precision A)
    gemm_mma<1, 0><<<ntm * ntn, NTHREADS, SMEM_TOTAL>>>(
        (const __half*)pvh, nullptr, (const __half*)psh,
        (float*)pc, nullptr, ntn);

    // scan over T (y written in-place into g_c), then LN
    scan_kernel<<<(BB * DD) / 256, 256>>>();
    ln_kernel<<<MROWS, 256>>>(gamma, beta, out);
}